// round 8
// baseline (speedup 1.0000x reference)
#include <cuda_runtime.h>
#include <math.h>
#include <stdint.h>

// ---------------------------------------------------------------------------
// Fixed problem shapes (fast path: uniform peaks)
// ---------------------------------------------------------------------------
#define BATCH      2
#define NUM_PEAKS  64
#define PEAKS      128          // BATCH * NUM_PEAKS
#define PSIZE      1000
#define MOTIF      640
#define HID        256
#define DEPTH      7
#define PROF_K     75
#define MAXLEN     1008         // padded row stride (floats)
#define GL_TOTAL   128000       // BATCH * NUM_PEAKS * PSIZE

// conv dynamic smem partition (bytes): 3-stage pipeline
#define WSM_STRIDE 28                            // floats per co row (24 used)
#define WSM_BYTES  (3 * 128 * WSM_STRIDE * 4)    // 43008
#define XS_BYTES   (3 * 8 * 384 * 4)             // 36864
#define CONV_SMEM  (WSM_BYTES + XS_BYTES)        // 79872 (x2 CTA = 156KB)

// Ping-pong activation buffers: [2][peak][channel][MAXLEN]
__device__ float g_buf[2][PEAKS * HID * MAXLEN];
// Per-(peak, channel) mean of the final feature map
__device__ float g_mean[PEAKS * HID];

__device__ __forceinline__ float softplus_f(float x) {
    return (x > 20.f) ? x : log1pf(expf(x));
}

// Packed dual-fp32 FMA (sm_100+): d = a*b + c on both 32-bit halves
__device__ __forceinline__ unsigned long long ffma2(unsigned long long a,
                                                    unsigned long long b,
                                                    unsigned long long c) {
    unsigned long long d;
    asm("fma.rn.f32x2 %0, %1, %2, %3;" : "=l"(d) : "l"(a), "l"(b), "l"(c));
    return d;
}

// duplicate one fp32 into both halves of a 64-bit pair
__device__ __forceinline__ unsigned long long dupf(float w) {
    unsigned long long d;
    asm("mov.b64 %0, {%1, %1};" : "=l"(d) : "f"(w));
    return d;
}

__device__ __forceinline__ float2 u2f2(unsigned long long u) {
    float2 f;
    asm("mov.b64 {%0, %1}, %2;" : "=f"(f.x), "=f"(f.y) : "l"(u));
    return f;
}

// cp.async helpers
__device__ __forceinline__ void cpa8(uint32_t dst, const void* src, int sz) {
    asm volatile("cp.async.ca.shared.global [%0], [%1], 8, %2;"
                 :: "r"(dst), "l"(src), "r"(sz));
}
__device__ __forceinline__ void cpa16(uint32_t dst, const void* src) {
    asm volatile("cp.async.ca.shared.global [%0], [%1], 16;"
                 :: "r"(dst), "l"(src));
}
__device__ __forceinline__ void cpa_commit() {
    asm volatile("cp.async.commit_group;");
}
template <int N>
__device__ __forceinline__ void cpa_wait() {
    asm volatile("cp.async.wait_group %0;" :: "n"(N));
}

// ---------------------------------------------------------------------------
// Kernel 1: 1x1 motif projection  h[n][c][l] = sum_m x[gl][m] * w[c][m] + b[c]
// 128 gl x 128 c per block, 256 threads; scalar weights + register dup.
// ---------------------------------------------------------------------------
__global__ __launch_bounds__(256)
void proj_kernel(const float* __restrict__ x,
                 const float* __restrict__ w,
                 const float* __restrict__ bias) {
    __shared__ float Ws[8][128];                   // [m][c] scalar
    __shared__ __align__(16) float Xs[8][128];     // [m][gl]

    const int tid = threadIdx.x;
    const int tx  = tid & 15;       // gl-pair lane
    const int ty  = tid >> 4;       // c lane
    const int gl0 = blockIdx.x * 128;
    const int c0  = blockIdx.y * 128;

    unsigned long long acc[8][4];
#pragma unroll
    for (int i = 0; i < 8; i++)
#pragma unroll
        for (int j = 0; j < 4; j++) acc[i][j] = 0ull;

    const int lc = tid >> 1;
    const int lm = (tid & 1) * 4;

    for (int m0 = 0; m0 < MOTIF; m0 += 8) {
        float4 wv4 = *(const float4*)&w[(c0 + lc) * MOTIF + m0 + lm];
        Ws[lm + 0][lc] = wv4.x;
        Ws[lm + 1][lc] = wv4.y;
        Ws[lm + 2][lc] = wv4.z;
        Ws[lm + 3][lc] = wv4.w;
        float4 xv4 = *(const float4*)&x[(size_t)(gl0 + lc) * MOTIF + m0 + lm];
        Xs[lm + 0][lc] = xv4.x;
        Xs[lm + 1][lc] = xv4.y;
        Xs[lm + 2][lc] = xv4.z;
        Xs[lm + 3][lc] = xv4.w;
        __syncthreads();

#pragma unroll
        for (int mm = 0; mm < 8; mm++) {
            const unsigned long long* xrow =
                reinterpret_cast<const unsigned long long*>(Xs[mm]);
            unsigned long long x2v[4];
#pragma unroll
            for (int j = 0; j < 4; j++) x2v[j] = xrow[tx + j * 16];
#pragma unroll
            for (int i = 0; i < 8; i++) {
                const unsigned long long wd = dupf(Ws[mm][ty + i * 16]);
#pragma unroll
                for (int j = 0; j < 4; j++)
                    acc[i][j] = ffma2(wd, x2v[j], acc[i][j]);
            }
        }
        __syncthreads();
    }

#pragma unroll
    for (int i = 0; i < 8; i++) {
        const int c = c0 + ty + i * 16;
        const float bv = bias[c];
#pragma unroll
        for (int j = 0; j < 4; j++) {
            const int gl = gl0 + tx * 2 + j * 32;
            const int n  = gl / PSIZE;
            const int l  = gl - n * PSIZE;
            float2 a = u2f2(acc[i][j]);
            a.x += bv; a.y += bv;
            *(float2*)&g_buf[0][((size_t)n * HID + c) * MAXLEN + l] = a;
        }
    }
}

// ---------------------------------------------------------------------------
// Kernel 2: dilated conv (K=3) + bias + ReLU + residual, f32x2 math.
// Fully templated on <DIL, LEN_IN, LEN_OUT>: all address math const-folded,
// loader has no divisions. 3-stage cp.async pipeline with wait_group 1 so the
// in-flight group's tail is never on the critical path.
// Block: 128 co x 128 l per peak; CI chunks of 8.
// ---------------------------------------------------------------------------
template <int DIL, int LEN_IN, int LEN_OUT>
__global__ __launch_bounds__(256, 2)
void conv_kernel(int src,
                 const float* __restrict__ w,     // [co][ci][3] this layer
                 const float* __restrict__ bias)  // [co]
{
    constexpr int SPAN2 = 64 + DIL;   // u64 elems per Xs row (<=192 < 256)
    constexpr int KD2   = DIL >> 1;   // per-k tap offset in u64 units

    extern __shared__ __align__(16) char smraw[];
    float (*Wsm)[128][WSM_STRIDE] = (float(*)[128][WSM_STRIDE])smraw;
    float (*Xs)[8][384]           = (float(*)[8][384])(smraw + WSM_BYTES);

    const float* __restrict__ in  = g_buf[src];
    float* __restrict__       out = g_buf[src ^ 1];

    const int tid = threadIdx.x;
    const int tx  = tid & 15;        // l-pair lane
    const int ty  = tid >> 4;        // co lane
    const int l0  = blockIdx.x * 128;
    const int co0 = blockIdx.y * 128;
    const int n   = blockIdx.z;

    const int wco  = tid >> 1;             // 0..127
    const int woff = (tid & 1) * 12;       // 0 or 12

    const uint32_t xs_sa  = (uint32_t)__cvta_generic_to_shared(&Xs[0][0][0]);
    const uint32_t wsm_sa = (uint32_t)__cvta_generic_to_shared(&Wsm[0][0][0]);
    const float* rowbase  = &in[(size_t)n * HID * MAXLEN];
    const float* wbase    = &w[(size_t)(co0 + wco) * (HID * 3) + woff];

    unsigned long long acc[8][4];
#pragma unroll
    for (int i = 0; i < 8; i++)
#pragma unroll
        for (int j = 0; j < 4; j++) acc[i][j] = 0ull;

    // ---- pipeline stage: issue cp.async for chunk -> buffer b --------------
    // Division-free: tid < SPAN2 threads each fetch one u64 per Xs row.
    auto issue_loads = [&](int chunk, int b) {
        const float* wp = wbase + chunk * 24;
        const uint32_t wdst =
            wsm_sa + (uint32_t)((b * 128 + wco) * WSM_STRIDE + woff) * 4u;
        cpa16(wdst,      wp);
        cpa16(wdst + 16, wp + 4);
        cpa16(wdst + 32, wp + 8);
        if (tid < SPAN2) {
            const int g  = l0 + 2 * tid;                 // even offset
            const int sz = (g < LEN_IN) ? 8 : 0;         // zfill pad
            const float* rb = rowbase + (size_t)(chunk * 8) * MAXLEN + g;
            const uint32_t xb =
                xs_sa + (uint32_t)(b * (8 * 384) + 2 * tid) * 4u;
#pragma unroll
            for (int ci = 0; ci < 8; ci++)
                cpa8(xb + (uint32_t)(ci * 384) * 4u, rb + (size_t)ci * MAXLEN,
                     sz);
        }
        cpa_commit();
    };

    // ---- prologue: chunks 0,1 in flight ------------------------------------
    issue_loads(0, 0);
    issue_loads(1, 1);
    cpa_wait<1>();        // chunk 0 resident; chunk 1 may still fly
    __syncthreads();

    // ---- main pipelined loop over 32 ci-chunks -----------------------------
    for (int c = 0; c < 32; c++) {
        const int cur = c - (c / 3) * 3;        // c % 3 (cheap, small range)

        // math on current chunk
#pragma unroll
        for (int ci = 0; ci < 8; ci++) {
            const unsigned long long* xrow =
                reinterpret_cast<const unsigned long long*>(Xs[cur][ci]);
#pragma unroll
            for (int k = 0; k < 3; k++) {
                unsigned long long x2v[4];
#pragma unroll
                for (int j = 0; j < 4; j++)
                    x2v[j] = xrow[tx + j * 16 + k * KD2];
#pragma unroll
                for (int i = 0; i < 8; i++) {
                    const unsigned long long wd =
                        dupf(Wsm[cur][ty + i * 16][ci * 3 + k]);
#pragma unroll
                    for (int j = 0; j < 4; j++)
                        acc[i][j] = ffma2(wd, x2v[j], acc[i][j]);
                }
            }
        }

        if (c + 2 < 32) {
            const int nb = (c + 2) - ((c + 2) / 3) * 3;
            issue_loads(c + 2, nb);     // buffer of chunk c-1 (done last iter)
            cpa_wait<1>();              // chunk c+1 resident
        } else {
            cpa_wait<0>();              // drain tail (chunk 31 resident)
        }
        __syncthreads();
    }

    // ---- epilogue: bias + relu + residual (middle tap), float2 I/O ---------
#pragma unroll
    for (int i = 0; i < 8; i++) {
        const int co = co0 + ty + i * 16;
        const float bv = bias[co];
        const float* resrow = &in[((size_t)n * HID + co) * MAXLEN];
        float* outrow = &out[((size_t)n * HID + co) * MAXLEN];
#pragma unroll
        for (int j = 0; j < 4; j++) {
            const int l = l0 + tx * 2 + j * 32;   // even; LEN_OUT even
            if (l < LEN_OUT) {
                float2 a = u2f2(acc[i][j]);
                float2 r = *(const float2*)&resrow[l + DIL];  // DIL even
                float2 v;
                v.x = fmaxf(a.x + bv, 0.f) + r.x;
                v.y = fmaxf(a.y + bv, 0.f) + r.y;
                *(float2*)&outrow[l] = v;
            }
        }
    }
}

// ---------------------------------------------------------------------------
// Kernel 3: per-(peak, channel) mean over length
// ---------------------------------------------------------------------------
__global__ __launch_bounds__(256)
void mean_kernel(int src, int len) {
    const float* __restrict__ in = g_buf[src];
    const int row  = blockIdx.x * 8 + (threadIdx.x >> 5);
    const int lane = threadIdx.x & 31;
    const float* p = in + (size_t)row * MAXLEN;
    float s = 0.f;
    for (int l = lane; l < len; l += 32) s += p[l];
#pragma unroll
    for (int o = 16; o; o >>= 1) s += __shfl_xor_sync(0xFFFFFFFFu, s, o);
    if (lane == 0) g_mean[row] = s / (float)len;
}

// ---------------------------------------------------------------------------
// Kernel 4: atpm head  out[n] = softplus(dot(mean[n], w_atpm) + b_atpm)
// ---------------------------------------------------------------------------
__global__ __launch_bounds__(256)
void atpm_kernel(const float* __restrict__ w, const float* __restrict__ b,
                 float* __restrict__ out) {
    __shared__ float sh[256];
    const int n = blockIdx.x;
    const int t = threadIdx.x;
    sh[t] = g_mean[n * HID + t] * w[t];
    __syncthreads();
    for (int s = 128; s > 0; s >>= 1) {
        if (t < s) sh[t] += sh[t + s];
        __syncthreads();
    }
    if (t == 0) out[n] = softplus_f(sh[0] + b[0]);
}

// ---------------------------------------------------------------------------
// Kernel 5: profile conv (K=75, 256 -> 1) + softplus
// ---------------------------------------------------------------------------
__global__ __launch_bounds__(256)
void prof_kernel(int src, const float* __restrict__ wp,
                 const float* __restrict__ bp, float* __restrict__ out,
                 int len_in, int len_out) {
    __shared__ float hrow[512];
    __shared__ float wrow[80];
    const float* __restrict__ in = g_buf[src];
    const int n = blockIdx.x;
    const int t = threadIdx.x;
    const int l0 = t;
    const int l1 = t + 256;

    float acc0 = 0.f, acc1 = 0.f;
    for (int c = 0; c < HID; c++) {
        for (int l = t; l < len_in; l += 256)
            hrow[l] = in[((size_t)n * HID + c) * MAXLEN + l];
        if (t < PROF_K) wrow[t] = wp[c * PROF_K + t];
        __syncthreads();

#pragma unroll 5
        for (int k = 0; k < PROF_K; k++)
            acc0 = fmaf(hrow[l0 + k], wrow[k], acc0);
        if (l1 < len_out) {
#pragma unroll 5
            for (int k = 0; k < PROF_K; k++)
                acc1 = fmaf(hrow[l1 + k], wrow[k], acc1);
        }
        __syncthreads();
    }
    const float bv = bp[0];
    out[PEAKS + (size_t)n * len_out + l0] = softplus_f(acc0 + bv);
    if (l1 < len_out)
        out[PEAKS + (size_t)n * len_out + l1] = softplus_f(acc1 + bv);
}

// ---------------------------------------------------------------------------
// Launch
// ---------------------------------------------------------------------------
template <int DIL, int LEN_IN, int LEN_OUT>
static void launch_conv(int src, const float* w, const float* b) {
    static bool attr_done = false;
    if (!attr_done) {
        cudaFuncSetAttribute(conv_kernel<DIL, LEN_IN, LEN_OUT>,
                             cudaFuncAttributeMaxDynamicSharedMemorySize,
                             CONV_SMEM);
        attr_done = true;
    }
    conv_kernel<DIL, LEN_IN, LEN_OUT>
        <<<dim3((LEN_OUT + 127) / 128, HID / 128, PEAKS), 256, CONV_SMEM>>>(
            src, w, b);
}

extern "C" void kernel_launch(void* const* d_in, const int* in_sizes, int n_in,
                              void* d_out, int out_size) {
    const float* x = (const float*)d_in[0];

    int iw = -1;
    for (int i = 1; i < n_in; i++)
        if (in_sizes[i] == MOTIF * HID) { iw = i; break; }

    const float* w_proj = (const float*)d_in[iw + 0];
    const float* b_proj = (const float*)d_in[iw + 1];
    const float* w_dil  = (const float*)d_in[iw + 2];
    const float* b_dil  = (const float*)d_in[iw + 3];
    const float* w_prof = (const float*)d_in[iw + 4];
    const float* b_prof = (const float*)d_in[iw + 5];
    const float* w_atpm = (const float*)d_in[iw + 6];
    const float* b_atpm = (const float*)d_in[iw + 7];
    float* out = (float*)d_out;

    const size_t WL = (size_t)HID * HID * 3;

    // 1) projection -> g_buf[0]
    proj_kernel<<<dim3(GL_TOTAL / 128, HID / 128), 256>>>(x, w_proj, b_proj);

    // 2) dilated conv tower (ping-pong), lengths: 1000->996->988->972->940->
    //    876->748->492, dilations 2..128
    launch_conv<  2, 1000, 996>(0, w_dil + 0 * WL, b_dil + 0 * HID);
    launch_conv<  4,  996, 988>(1, w_dil + 1 * WL, b_dil + 1 * HID);
    launch_conv<  8,  988, 972>(0, w_dil + 2 * WL, b_dil + 2 * HID);
    launch_conv< 16,  972, 940>(1, w_dil + 3 * WL, b_dil + 3 * HID);
    launch_conv< 32,  940, 876>(0, w_dil + 4 * WL, b_dil + 4 * HID);
    launch_conv< 64,  876, 748>(1, w_dil + 5 * WL, b_dil + 5 * HID);
    launch_conv<128,  748, 492>(0, w_dil + 6 * WL, b_dil + 6 * HID);
    const int src = 1;   // final map lives in g_buf[1], len = 492
    const int len = 492;

    // 3) mean over length
    mean_kernel<<<(PEAKS * HID) / 8, 256>>>(src, len);

    // 4) atpm head -> out[0..127]
    atpm_kernel<<<PEAKS, 256>>>(w_atpm, b_atpm, out);

    // 5) profile conv -> out[128 .. 128 + 128*418)
    prof_kernel<<<PEAKS, 256>>>(src, w_prof, b_prof, out, len, len - PROF_K + 1);
}

// round 9
// speedup vs baseline: 1.5948x; 1.5948x over previous
#include <cuda_runtime.h>
#include <math.h>
#include <stdint.h>

// ---------------------------------------------------------------------------
// Fixed problem shapes (fast path: uniform peaks)
// ---------------------------------------------------------------------------
#define BATCH      2
#define NUM_PEAKS  64
#define PEAKS      128          // BATCH * NUM_PEAKS
#define PSIZE      1000
#define MOTIF      640
#define HID        256
#define DEPTH      7
#define PROF_K     75
#define MAXLEN     1008         // padded row stride (floats)
#define GL_TOTAL   128000       // BATCH * NUM_PEAKS * PSIZE

// conv dynamic smem partition (bytes): 2-stage pipeline (R7 layout)
#define WSM_STRIDE 28                            // floats per co row (24 used)
#define WSM_BYTES  (2 * 128 * WSM_STRIDE * 4)    // 28672
#define XS_BYTES   (2 * 8 * 384 * 4)             // 24576
#define CONV_SMEM  (WSM_BYTES + XS_BYTES)        // 53248

// Ping-pong activation buffers: [2][peak][channel][MAXLEN]
__device__ float g_buf[2][PEAKS * HID * MAXLEN];
// Per-(peak, channel) mean of the final feature map
__device__ float g_mean[PEAKS * HID];

__device__ __forceinline__ float softplus_f(float x) {
    return (x > 20.f) ? x : log1pf(expf(x));
}

// Packed dual-fp32 FMA (sm_100+): d = a*b + c on both 32-bit halves
__device__ __forceinline__ unsigned long long ffma2(unsigned long long a,
                                                    unsigned long long b,
                                                    unsigned long long c) {
    unsigned long long d;
    asm("fma.rn.f32x2 %0, %1, %2, %3;" : "=l"(d) : "l"(a), "l"(b), "l"(c));
    return d;
}

// duplicate one fp32 into both halves of a 64-bit pair
__device__ __forceinline__ unsigned long long dupf(float w) {
    unsigned long long d;
    asm("mov.b64 %0, {%1, %1};" : "=l"(d) : "f"(w));
    return d;
}

__device__ __forceinline__ float2 u2f2(unsigned long long u) {
    float2 f;
    asm("mov.b64 {%0, %1}, %2;" : "=f"(f.x), "=f"(f.y) : "l"(u));
    return f;
}

// cp.async helpers
__device__ __forceinline__ void cpa8(uint32_t dst, const void* src, int sz) {
    asm volatile("cp.async.ca.shared.global [%0], [%1], 8, %2;"
                 :: "r"(dst), "l"(src), "r"(sz));
}
__device__ __forceinline__ void cpa16(uint32_t dst, const void* src) {
    asm volatile("cp.async.ca.shared.global [%0], [%1], 16;"
                 :: "r"(dst), "l"(src));
}
__device__ __forceinline__ void cpa_commit() {
    asm volatile("cp.async.commit_group;");
}
__device__ __forceinline__ void cpa_wait0() {
    asm volatile("cp.async.wait_group 0;");
}

// ---------------------------------------------------------------------------
// Kernel 1: 1x1 motif projection  h[n][c][l] = sum_m x[gl][m] * w[c][m] + b[c]
// 128 gl x 128 c per block, 256 threads; scalar weights + register dup.
// ---------------------------------------------------------------------------
__global__ __launch_bounds__(256)
void proj_kernel(const float* __restrict__ x,
                 const float* __restrict__ w,
                 const float* __restrict__ bias) {
    __shared__ float Ws[8][128];                   // [m][c] scalar
    __shared__ __align__(16) float Xs[8][128];     // [m][gl]

    const int tid = threadIdx.x;
    const int tx  = tid & 15;       // gl-pair lane
    const int ty  = tid >> 4;       // c lane
    const int gl0 = blockIdx.x * 128;
    const int c0  = blockIdx.y * 128;

    unsigned long long acc[8][4];
#pragma unroll
    for (int i = 0; i < 8; i++)
#pragma unroll
        for (int j = 0; j < 4; j++) acc[i][j] = 0ull;

    const int lc = tid >> 1;
    const int lm = (tid & 1) * 4;

    for (int m0 = 0; m0 < MOTIF; m0 += 8) {
        float4 wv4 = *(const float4*)&w[(c0 + lc) * MOTIF + m0 + lm];
        Ws[lm + 0][lc] = wv4.x;
        Ws[lm + 1][lc] = wv4.y;
        Ws[lm + 2][lc] = wv4.z;
        Ws[lm + 3][lc] = wv4.w;
        float4 xv4 = *(const float4*)&x[(size_t)(gl0 + lc) * MOTIF + m0 + lm];
        Xs[lm + 0][lc] = xv4.x;
        Xs[lm + 1][lc] = xv4.y;
        Xs[lm + 2][lc] = xv4.z;
        Xs[lm + 3][lc] = xv4.w;
        __syncthreads();

#pragma unroll
        for (int mm = 0; mm < 8; mm++) {
            const unsigned long long* xrow =
                reinterpret_cast<const unsigned long long*>(Xs[mm]);
            unsigned long long x2v[4];
#pragma unroll
            for (int j = 0; j < 4; j++) x2v[j] = xrow[tx + j * 16];
#pragma unroll
            for (int i = 0; i < 8; i++) {
                const unsigned long long wd = dupf(Ws[mm][ty + i * 16]);
#pragma unroll
                for (int j = 0; j < 4; j++)
                    acc[i][j] = ffma2(wd, x2v[j], acc[i][j]);
            }
        }
        __syncthreads();
    }

#pragma unroll
    for (int i = 0; i < 8; i++) {
        const int c = c0 + ty + i * 16;
        const float bv = bias[c];
#pragma unroll
        for (int j = 0; j < 4; j++) {
            const int gl = gl0 + tx * 2 + j * 32;
            const int n  = gl / PSIZE;
            const int l  = gl - n * PSIZE;
            float2 a = u2f2(acc[i][j]);
            a.x += bv; a.y += bv;
            *(float2*)&g_buf[0][((size_t)n * HID + c) * MAXLEN + l] = a;
        }
    }
}

// ---------------------------------------------------------------------------
// Kernel 2: dilated conv (K=3) + bias + ReLU + residual, f32x2 math.
// R7-proven structure: 2-stage double buffer, cp.async, wait_group 0,
// loader spread over all 256 threads. Templated on <DIL, LEN_IN, LEN_OUT>
// so the loader's divisor and all tap offsets are compile-time constants
// (kills the runtime-IDIV sequences that showed up as alu ~10%).
// Block: 128 co x 128 l per peak; CI chunks of 8.
// ---------------------------------------------------------------------------
template <int DIL, int LEN_IN, int LEN_OUT>
__global__ __launch_bounds__(256, 2)
void conv_kernel(int src,
                 const float* __restrict__ w,     // [co][ci][3] this layer
                 const float* __restrict__ bias)  // [co]
{
    constexpr int SPAN2   = 64 + DIL;    // u64 elems per Xs row (<=192)
    constexpr int KD2     = DIL >> 1;    // per-k tap offset in u64 units
    constexpr int TOTAL64 = 8 * SPAN2;

    extern __shared__ __align__(16) char smraw[];
    float (*Wsm)[128][WSM_STRIDE] = (float(*)[128][WSM_STRIDE])smraw;
    float (*Xs)[8][384]           = (float(*)[8][384])(smraw + WSM_BYTES);

    const float* __restrict__ in  = g_buf[src];
    float* __restrict__       out = g_buf[src ^ 1];

    const int tid = threadIdx.x;
    const int tx  = tid & 15;        // l-pair lane
    const int ty  = tid >> 4;        // co lane
    const int l0  = blockIdx.x * 128;
    const int co0 = blockIdx.y * 128;
    const int n   = blockIdx.z;

    const int wco  = tid >> 1;             // 0..127
    const int woff = (tid & 1) * 12;       // 0 or 12

    const uint32_t xs_sa  = (uint32_t)__cvta_generic_to_shared(&Xs[0][0][0]);
    const uint32_t wsm_sa = (uint32_t)__cvta_generic_to_shared(&Wsm[0][0][0]);
    const float* rowbase  = &in[(size_t)n * HID * MAXLEN];
    const float* wbase    = &w[(size_t)(co0 + wco) * (HID * 3) + woff];

    unsigned long long acc[8][4];
#pragma unroll
    for (int i = 0; i < 8; i++)
#pragma unroll
        for (int j = 0; j < 4; j++) acc[i][j] = 0ull;

    // ---- pipeline stage: issue cp.async for chunk -> buffer b --------------
    // Spread across all 256 threads; e/SPAN2 is division by a compile-time
    // constant (mul-shift, no IDIV).
    auto issue_loads = [&](int chunk, int b) {
        const float* wp = wbase + chunk * 24;
        const uint32_t wdst =
            wsm_sa + (uint32_t)((b * 128 + wco) * WSM_STRIDE + woff) * 4u;
        cpa16(wdst,      wp);
        cpa16(wdst + 16, wp + 4);
        cpa16(wdst + 32, wp + 8);
        const float* rb = rowbase + (size_t)(chunk * 8) * MAXLEN;
        const uint32_t xb = xs_sa + (uint32_t)b * (8 * 384 * 4);
#pragma unroll
        for (int e = tid; e < TOTAL64; e += 256) {
            const int ci = e / SPAN2;                 // const divisor
            const int p  = e - ci * SPAN2;
            const int g  = l0 + 2 * p;
            cpa8(xb + (uint32_t)(ci * 384 + 2 * p) * 4u,
                 rb + (size_t)ci * MAXLEN + g,
                 (g < LEN_IN) ? 8 : 0);
        }
        cpa_commit();
    };

    // ---- prologue: chunk 0 -------------------------------------------------
    issue_loads(0, 0);
    cpa_wait0();
    __syncthreads();

    // ---- main pipelined loop over 32 ci-chunks -----------------------------
    for (int c = 0; c < 32; c++) {
        const int cur = c & 1;
        if (c < 31) issue_loads(c + 1, cur ^ 1);

        // math on current chunk
#pragma unroll
        for (int ci = 0; ci < 8; ci++) {
            const unsigned long long* xrow =
                reinterpret_cast<const unsigned long long*>(Xs[cur][ci]);
#pragma unroll
            for (int k = 0; k < 3; k++) {
                unsigned long long x2v[4];
#pragma unroll
                for (int j = 0; j < 4; j++)
                    x2v[j] = xrow[tx + j * 16 + k * KD2];
#pragma unroll
                for (int i = 0; i < 8; i++) {
                    const unsigned long long wd =
                        dupf(Wsm[cur][ty + i * 16][ci * 3 + k]);
#pragma unroll
                    for (int j = 0; j < 4; j++)
                        acc[i][j] = ffma2(wd, x2v[j], acc[i][j]);
                }
            }
        }

        if (c < 31) cpa_wait0();   // next chunk arrived (overlapped w/ math)
        __syncthreads();
    }

    // ---- epilogue: bias + relu + residual (middle tap), float2 I/O ---------
#pragma unroll
    for (int i = 0; i < 8; i++) {
        const int co = co0 + ty + i * 16;
        const float bv = bias[co];
        const float* resrow = &in[((size_t)n * HID + co) * MAXLEN];
        float* outrow = &out[((size_t)n * HID + co) * MAXLEN];
#pragma unroll
        for (int j = 0; j < 4; j++) {
            const int l = l0 + tx * 2 + j * 32;   // even; LEN_OUT even
            if (l < LEN_OUT) {
                float2 a = u2f2(acc[i][j]);
                float2 r = *(const float2*)&resrow[l + DIL];  // DIL even
                float2 v;
                v.x = fmaxf(a.x + bv, 0.f) + r.x;
                v.y = fmaxf(a.y + bv, 0.f) + r.y;
                *(float2*)&outrow[l] = v;
            }
        }
    }
}

// ---------------------------------------------------------------------------
// Kernel 3: per-(peak, channel) mean over length
// ---------------------------------------------------------------------------
__global__ __launch_bounds__(256)
void mean_kernel(int src, int len) {
    const float* __restrict__ in = g_buf[src];
    const int row  = blockIdx.x * 8 + (threadIdx.x >> 5);
    const int lane = threadIdx.x & 31;
    const float* p = in + (size_t)row * MAXLEN;
    float s = 0.f;
    for (int l = lane; l < len; l += 32) s += p[l];
#pragma unroll
    for (int o = 16; o; o >>= 1) s += __shfl_xor_sync(0xFFFFFFFFu, s, o);
    if (lane == 0) g_mean[row] = s / (float)len;
}

// ---------------------------------------------------------------------------
// Kernel 4: atpm head  out[n] = softplus(dot(mean[n], w_atpm) + b_atpm)
// ---------------------------------------------------------------------------
__global__ __launch_bounds__(256)
void atpm_kernel(const float* __restrict__ w, const float* __restrict__ b,
                 float* __restrict__ out) {
    __shared__ float sh[256];
    const int n = blockIdx.x;
    const int t = threadIdx.x;
    sh[t] = g_mean[n * HID + t] * w[t];
    __syncthreads();
    for (int s = 128; s > 0; s >>= 1) {
        if (t < s) sh[t] += sh[t + s];
        __syncthreads();
    }
    if (t == 0) out[n] = softplus_f(sh[0] + b[0]);
}

// ---------------------------------------------------------------------------
// Kernel 5: profile conv (K=75, 256 -> 1) + softplus
// ---------------------------------------------------------------------------
__global__ __launch_bounds__(256)
void prof_kernel(int src, const float* __restrict__ wp,
                 const float* __restrict__ bp, float* __restrict__ out,
                 int len_in, int len_out) {
    __shared__ float hrow[512];
    __shared__ float wrow[80];
    const float* __restrict__ in = g_buf[src];
    const int n = blockIdx.x;
    const int t = threadIdx.x;
    const int l0 = t;
    const int l1 = t + 256;

    float acc0 = 0.f, acc1 = 0.f;
    for (int c = 0; c < HID; c++) {
        for (int l = t; l < len_in; l += 256)
            hrow[l] = in[((size_t)n * HID + c) * MAXLEN + l];
        if (t < PROF_K) wrow[t] = wp[c * PROF_K + t];
        __syncthreads();

#pragma unroll 5
        for (int k = 0; k < PROF_K; k++)
            acc0 = fmaf(hrow[l0 + k], wrow[k], acc0);
        if (l1 < len_out) {
#pragma unroll 5
            for (int k = 0; k < PROF_K; k++)
                acc1 = fmaf(hrow[l1 + k], wrow[k], acc1);
        }
        __syncthreads();
    }
    const float bv = bp[0];
    out[PEAKS + (size_t)n * len_out + l0] = softplus_f(acc0 + bv);
    if (l1 < len_out)
        out[PEAKS + (size_t)n * len_out + l1] = softplus_f(acc1 + bv);
}

// ---------------------------------------------------------------------------
// Launch
// ---------------------------------------------------------------------------
template <int DIL, int LEN_IN, int LEN_OUT>
static void launch_conv(int src, const float* w, const float* b) {
    static bool attr_done = false;
    if (!attr_done) {
        cudaFuncSetAttribute(conv_kernel<DIL, LEN_IN, LEN_OUT>,
                             cudaFuncAttributeMaxDynamicSharedMemorySize,
                             CONV_SMEM);
        attr_done = true;
    }
    conv_kernel<DIL, LEN_IN, LEN_OUT>
        <<<dim3((LEN_OUT + 127) / 128, HID / 128, PEAKS), 256, CONV_SMEM>>>(
            src, w, b);
}

extern "C" void kernel_launch(void* const* d_in, const int* in_sizes, int n_in,
                              void* d_out, int out_size) {
    const float* x = (const float*)d_in[0];

    int iw = -1;
    for (int i = 1; i < n_in; i++)
        if (in_sizes[i] == MOTIF * HID) { iw = i; break; }

    const float* w_proj = (const float*)d_in[iw + 0];
    const float* b_proj = (const float*)d_in[iw + 1];
    const float* w_dil  = (const float*)d_in[iw + 2];
    const float* b_dil  = (const float*)d_in[iw + 3];
    const float* w_prof = (const float*)d_in[iw + 4];
    const float* b_prof = (const float*)d_in[iw + 5];
    const float* w_atpm = (const float*)d_in[iw + 6];
    const float* b_atpm = (const float*)d_in[iw + 7];
    float* out = (float*)d_out;

    const size_t WL = (size_t)HID * HID * 3;

    // 1) projection -> g_buf[0]
    proj_kernel<<<dim3(GL_TOTAL / 128, HID / 128), 256>>>(x, w_proj, b_proj);

    // 2) dilated conv tower (ping-pong), lengths: 1000->996->988->972->940->
    //    876->748->492, dilations 2..128
    launch_conv<  2, 1000, 996>(0, w_dil + 0 * WL, b_dil + 0 * HID);
    launch_conv<  4,  996, 988>(1, w_dil + 1 * WL, b_dil + 1 * HID);
    launch_conv<  8,  988, 972>(0, w_dil + 2 * WL, b_dil + 2 * HID);
    launch_conv< 16,  972, 940>(1, w_dil + 3 * WL, b_dil + 3 * HID);
    launch_conv< 32,  940, 876>(0, w_dil + 4 * WL, b_dil + 4 * HID);
    launch_conv< 64,  876, 748>(1, w_dil + 5 * WL, b_dil + 5 * HID);
    launch_conv<128,  748, 492>(0, w_dil + 6 * WL, b_dil + 6 * HID);
    const int src = 1;   // final map lives in g_buf[1], len = 492
    const int len = 492;

    // 3) mean over length
    mean_kernel<<<(PEAKS * HID) / 8, 256>>>(src, len);

    // 4) atpm head -> out[0..127]
    atpm_kernel<<<PEAKS, 256>>>(w_atpm, b_atpm, out);

    // 5) profile conv -> out[128 .. 128 + 128*418)
    prof_kernel<<<PEAKS, 256>>>(src, w_prof, b_prof, out, len, len - PROF_K + 1);
}

// round 11
// speedup vs baseline: 1.7499x; 1.0973x over previous
#include <cuda_runtime.h>
#include <cuda_bf16.h>
#include <mma.h>
#include <math.h>
#include <stdint.h>

using namespace nvcuda;

// ---------------------------------------------------------------------------
// Fixed problem shapes (fast path: uniform peaks)
// ---------------------------------------------------------------------------
#define BATCH      2
#define NUM_PEAKS  64
#define PEAKS      128          // BATCH * NUM_PEAKS
#define PSIZE      1000
#define MOTIF      640
#define HID        256
#define DEPTH      7
#define PROF_K     75
#define MAXLEN     1008         // padded row stride (floats)
#define GL_TOTAL   128000       // BATCH * NUM_PEAKS * PSIZE
#define BUFSZ      (PEAKS * HID * MAXLEN)

// K layout: 48 chunks; chunk = 16 q -> 48 extended-K bf16 ([xh|xl|xh] vs [wh|wh|wl])
#define NCHUNK     48
#define CH_K       48           // extended K per chunk (3 x 16)

// conv smem layout (bytes): A stride 112B (56 bf16), B stride 96B (48 bf16)
#define A_STRIDE_E 56
#define A_BYTES    (128 * 112)                  // 14336
#define B_BYTES    (128 * 96)                   // 12288
#define SM_A0      0
#define SM_A1      A_BYTES
#define SM_B0      (2 * A_BYTES)                // 28672
#define SM_B1      (2 * A_BYTES + B_BYTES)      // 40960
#define D_LD       132                          // floats per co row (128 + 4)
#define D_BYTES    (128 * D_LD * 4)             // 67584 (unions A/B region)
#define CONV_SMEM  69632

// ---------------------------------------------------------------------------
// Global buffers
// ---------------------------------------------------------------------------
// fp32 activations (residual + heads), ping-pong; slack for benign over-reads
__device__ float g_buf[2][BUFSZ + 4096];
// packed split activations: u32 = (bf16 lo << 16) | bf16 hi, ping-pong
__device__ unsigned g_split[2][BUFSZ + 4096];
// pre-packed split conv weights: [layer][co][48 chunks * 48 bf16]
__device__ __nv_bfloat16 g_wpack[DEPTH][HID][NCHUNK * CH_K];
// per-(peak, channel) mean of the final feature map
__device__ float g_mean[PEAKS * HID];

__device__ __forceinline__ float softplus_f(float x) {
    return (x > 20.f) ? x : log1pf(expf(x));
}

// Packed dual-fp32 FMA (sm_100+)
__device__ __forceinline__ unsigned long long ffma2(unsigned long long a,
                                                    unsigned long long b,
                                                    unsigned long long c) {
    unsigned long long d;
    asm("fma.rn.f32x2 %0, %1, %2, %3;" : "=l"(d) : "l"(a), "l"(b), "l"(c));
    return d;
}
__device__ __forceinline__ unsigned long long dupf(float w) {
    unsigned long long d;
    asm("mov.b64 %0, {%1, %1};" : "=l"(d) : "f"(w));
    return d;
}
__device__ __forceinline__ float2 u2f2(unsigned long long u) {
    float2 f;
    asm("mov.b64 {%0, %1}, %2;" : "=f"(f.x), "=f"(f.y) : "l"(u));
    return f;
}

// hi/lo bf16 split, packed into one u32 (lo<<16 | hi)
__device__ __forceinline__ unsigned pack_split(float v) {
    __nv_bfloat16 h = __float2bfloat16(v);
    __nv_bfloat16 l = __float2bfloat16(v - __bfloat162float(h));
    unsigned short hu = *(unsigned short*)&h;
    unsigned short lu = *(unsigned short*)&l;
    return ((unsigned)lu << 16) | (unsigned)hu;
}

// cp.async helpers
__device__ __forceinline__ void cpa16(uint32_t dst, const void* src) {
    asm volatile("cp.async.ca.shared.global [%0], [%1], 16;"
                 :: "r"(dst), "l"(src));
}
__device__ __forceinline__ void cpa_commit() {
    asm volatile("cp.async.commit_group;");
}
__device__ __forceinline__ void cpa_wait0() {
    asm volatile("cp.async.wait_group 0;");
}

// ---------------------------------------------------------------------------
// Kernel 0: pack + split conv weights -> g_wpack
// chunk row: [wh(q0..15) | wh(q0..15) | wl(q0..15)]
// ---------------------------------------------------------------------------
__global__ __launch_bounds__(256)
void prep_w_kernel(const float* __restrict__ w_dil) {
    int idx = blockIdx.x * 256 + threadIdx.x;       // [0, 7*256*768)
    if (idx >= DEPTH * HID * 768) return;
    int q  = idx % 768;
    int co = (idx / 768) % HID;
    int L  = idx / (768 * HID);
    int ci = q / 3, k = q - 3 * ci;
    float v = w_dil[(((size_t)L * HID + co) * HID + ci) * 3 + k];
    __nv_bfloat16 hi = __float2bfloat16(v);
    __nv_bfloat16 lo = __float2bfloat16(v - __bfloat162float(hi));
    int c = q >> 4, t = q & 15;
    __nv_bfloat16* row = &g_wpack[L][co][c * CH_K];
    row[t]      = hi;
    row[16 + t] = hi;
    row[32 + t] = lo;
}

// ---------------------------------------------------------------------------
// Kernel 1: 1x1 motif projection (scalar f32x2, proven) + split emission
// ---------------------------------------------------------------------------
__global__ __launch_bounds__(256)
void proj_kernel(const float* __restrict__ x,
                 const float* __restrict__ w,
                 const float* __restrict__ bias) {
    __shared__ float Ws[8][128];
    __shared__ __align__(16) float Xs[8][128];

    const int tid = threadIdx.x;
    const int tx  = tid & 15;
    const int ty  = tid >> 4;
    const int gl0 = blockIdx.x * 128;
    const int c0  = blockIdx.y * 128;

    unsigned long long acc[8][4];
#pragma unroll
    for (int i = 0; i < 8; i++)
#pragma unroll
        for (int j = 0; j < 4; j++) acc[i][j] = 0ull;

    const int lc = tid >> 1;
    const int lm = (tid & 1) * 4;

    for (int m0 = 0; m0 < MOTIF; m0 += 8) {
        float4 wv4 = *(const float4*)&w[(c0 + lc) * MOTIF + m0 + lm];
        Ws[lm + 0][lc] = wv4.x;
        Ws[lm + 1][lc] = wv4.y;
        Ws[lm + 2][lc] = wv4.z;
        Ws[lm + 3][lc] = wv4.w;
        float4 xv4 = *(const float4*)&x[(size_t)(gl0 + lc) * MOTIF + m0 + lm];
        Xs[lm + 0][lc] = xv4.x;
        Xs[lm + 1][lc] = xv4.y;
        Xs[lm + 2][lc] = xv4.z;
        Xs[lm + 3][lc] = xv4.w;
        __syncthreads();

#pragma unroll
        for (int mm = 0; mm < 8; mm++) {
            const unsigned long long* xrow =
                reinterpret_cast<const unsigned long long*>(Xs[mm]);
            unsigned long long x2v[4];
#pragma unroll
            for (int j = 0; j < 4; j++) x2v[j] = xrow[tx + j * 16];
#pragma unroll
            for (int i = 0; i < 8; i++) {
                const unsigned long long wd = dupf(Ws[mm][ty + i * 16]);
#pragma unroll
                for (int j = 0; j < 4; j++)
                    acc[i][j] = ffma2(wd, x2v[j], acc[i][j]);
            }
        }
        __syncthreads();
    }

#pragma unroll
    for (int i = 0; i < 8; i++) {
        const int c = c0 + ty + i * 16;
        const float bv = bias[c];
#pragma unroll
        for (int j = 0; j < 4; j++) {
            const int gl = gl0 + tx * 2 + j * 32;
            const int n  = gl / PSIZE;
            const int l  = gl - n * PSIZE;
            float2 a = u2f2(acc[i][j]);
            a.x += bv; a.y += bv;
            const size_t off = ((size_t)n * HID + c) * MAXLEN + l;
            *(float2*)&g_buf[0][off] = a;
            uint2 sp;
            sp.x = pack_split(a.x);
            sp.y = pack_split(a.y);
            *(uint2*)&g_split[0][off] = sp;
        }
    }
}

// ---------------------------------------------------------------------------
// Kernel 2: dilated conv layer via WMMA bf16 (HMMA), 3-term hi/lo split.
// CTA = (l-tile 128, co-half 128, peak). 8 warps tile M128xN128 as 4x2
// warp-tiles of 32x64. Double-buffered A (built: LDG+PRMT+STS) and
// B (cp.async from g_wpack). Epilogue via smem D (unions A/B buffers).
// ---------------------------------------------------------------------------
template <int DIL, int LEN_OUT>
__global__ __launch_bounds__(256, 2)
void conv_wmma_kernel(int src, int layer, const float* __restrict__ bias) {
    extern __shared__ __align__(16) char smraw[];
    const uint32_t smb = (uint32_t)__cvta_generic_to_shared(smraw);

    const int tid    = threadIdx.x;
    const int wid    = tid >> 5;
    const int warp_m = wid & 3;          // 0..3 -> m0 = 32*warp_m
    const int warp_n = wid >> 2;         // 0..1 -> n0 = 64*warp_n
    const int l0     = blockIdx.x * 128;
    const int nh     = blockIdx.y;       // co half
    const int n      = blockIdx.z;       // peak

    const unsigned* __restrict__ xsrc = g_split[src] + (size_t)n * HID * MAXLEN;
    const float* __restrict__ resbase = g_buf[src] + (size_t)n * HID * MAXLEN;
    float* __restrict__ outbase   = g_buf[src ^ 1] + (size_t)n * HID * MAXLEN;
    unsigned* __restrict__ outsplit =
        g_split[src ^ 1] + (size_t)n * HID * MAXLEN;

    // A-build role: row l = tid&127, half h = tid>>7 (qq in [8h, 8h+8))
    const int al = tid & 127;
    const int ah = tid >> 7;
    // B-copy role: row co = tid>>1, 48B half = tid&1
    const int brow  = tid >> 1;
    const int bhalf = tid & 1;
    const __nv_bfloat16* wrow = &g_wpack[layer][nh * 128 + brow][0];

    wmma::fragment<wmma::accumulator, 16, 16, 16, float> acc[2][4];
#pragma unroll
    for (int mi = 0; mi < 2; mi++)
#pragma unroll
        for (int ni = 0; ni < 4; ni++) wmma::fill_fragment(acc[mi][ni], 0.f);

    unsigned areg[8];

    // ---- stage helpers -----------------------------------------------------
    auto issue_b = [&](int c, int b) {
        const uint32_t dst = smb + (b ? SM_B1 : SM_B0) + brow * 96 + bhalf * 48;
        const __nv_bfloat16* src_p = wrow + c * CH_K + bhalf * 24;
        cpa16(dst,      src_p);
        cpa16(dst + 16, src_p + 8);
        cpa16(dst + 32, src_p + 16);
        cpa_commit();
    };
    auto a_ld = [&](int c) {
#pragma unroll
        for (int j = 0; j < 8; j++) {
            const int q  = c * 16 + ah * 8 + j;
            const int ci = q / 3;
            const int k  = q - 3 * ci;
            areg[j] = xsrc[(size_t)ci * MAXLEN + l0 + al + k * DIL];
        }
    };
    auto a_st = [&](int b) {
        uint4 H, L;
        asm("prmt.b32 %0, %1, %2, 0x5410;" : "=r"(H.x) : "r"(areg[0]), "r"(areg[1]));
        asm("prmt.b32 %0, %1, %2, 0x5410;" : "=r"(H.y) : "r"(areg[2]), "r"(areg[3]));
        asm("prmt.b32 %0, %1, %2, 0x5410;" : "=r"(H.z) : "r"(areg[4]), "r"(areg[5]));
        asm("prmt.b32 %0, %1, %2, 0x5410;" : "=r"(H.w) : "r"(areg[6]), "r"(areg[7]));
        asm("prmt.b32 %0, %1, %2, 0x7632;" : "=r"(L.x) : "r"(areg[0]), "r"(areg[1]));
        asm("prmt.b32 %0, %1, %2, 0x7632;" : "=r"(L.y) : "r"(areg[2]), "r"(areg[3]));
        asm("prmt.b32 %0, %1, %2, 0x7632;" : "=r"(L.z) : "r"(areg[4]), "r"(areg[5]));
        asm("prmt.b32 %0, %1, %2, 0x7632;" : "=r"(L.w) : "r"(areg[6]), "r"(areg[7]));
        const uint32_t ab = smb + (b ? SM_A1 : SM_A0) + al * 112 + ah * 16;
#define STS4(off, v) \
        asm volatile("st.shared.v4.b32 [%0], {%1, %2, %3, %4};" \
            :: "r"(ab + (off)), "r"((v).x), "r"((v).y), "r"((v).z), "r"((v).w) \
            : "memory")
        STS4(0,  H);     // xh block, cols [0,16)
        STS4(32, L);     // xl block, cols [16,32)
        STS4(64, H);     // xh dup,  cols [32,48)
#undef STS4
    };

    // ---- prologue: chunk 0 -------------------------------------------------
    issue_b(0, 0);
    a_ld(0);
    a_st(0);
    cpa_wait0();
    __syncthreads();

    // ---- main loop over 48 chunks ------------------------------------------
    const __nv_bfloat16* As_all = reinterpret_cast<const __nv_bfloat16*>(smraw);
#pragma unroll 1
    for (int c = 0; c < NCHUNK; c++) {
        const int cb = c & 1;
        if (c + 1 < NCHUNK) {
            issue_b(c + 1, cb ^ 1);
            a_ld(c + 1);
        }

        const __nv_bfloat16* As =
            reinterpret_cast<const __nv_bfloat16*>(smraw + (cb ? SM_A1 : SM_A0));
        const __nv_bfloat16* Bs =
            reinterpret_cast<const __nv_bfloat16*>(smraw + (cb ? SM_B1 : SM_B0));

#pragma unroll
        for (int kb = 0; kb < 3; kb++) {
            wmma::fragment<wmma::matrix_a, 16, 16, 16, __nv_bfloat16,
                           wmma::row_major> afrag[2];
            wmma::fragment<wmma::matrix_b, 16, 16, 16, __nv_bfloat16,
                           wmma::col_major> bfrag[4];
#pragma unroll
            for (int mi = 0; mi < 2; mi++)
                wmma::load_matrix_sync(
                    afrag[mi],
                    As + (warp_m * 32 + mi * 16) * A_STRIDE_E + kb * 16,
                    A_STRIDE_E);
#pragma unroll
            for (int ni = 0; ni < 4; ni++)
                wmma::load_matrix_sync(
                    bfrag[ni],
                    Bs + (warp_n * 64 + ni * 16) * CH_K + kb * 16,
                    CH_K);
#pragma unroll
            for (int mi = 0; mi < 2; mi++)
#pragma unroll
                for (int ni = 0; ni < 4; ni++)
                    wmma::mma_sync(acc[mi][ni], afrag[mi], bfrag[ni],
                                   acc[mi][ni]);
        }

        if (c + 1 < NCHUNK) {
            a_st(cb ^ 1);
            cpa_wait0();
        }
        __syncthreads();
    }

    // ---- epilogue: acc -> smem D [co][l] (col_major store), then fused out -
    float* Ds = reinterpret_cast<float*>(smraw);   // unions dead A/B buffers
#pragma unroll
    for (int mi = 0; mi < 2; mi++)
#pragma unroll
        for (int ni = 0; ni < 4; ni++)
            wmma::store_matrix_sync(
                Ds + (warp_n * 64 + ni * 16) * D_LD + (warp_m * 32 + mi * 16),
                acc[mi][ni], D_LD, wmma::mem_col_major);
    __syncthreads();

#pragma unroll 1
    for (int idx = tid; idx < 128 * 128; idx += 256) {
        const int co = idx >> 7;           // 0..127 in this half
        const int l  = idx & 127;
        if (l0 + l < LEN_OUT) {
            const int co_g = nh * 128 + co;
            const float d  = Ds[co * D_LD + l];
            const float v  = fmaxf(d + bias[co_g], 0.f)
                           + resbase[(size_t)co_g * MAXLEN + l0 + l + DIL];
            outbase[(size_t)co_g * MAXLEN + l0 + l]  = v;
            outsplit[(size_t)co_g * MAXLEN + l0 + l] = pack_split(v);
        }
    }
}

// ---------------------------------------------------------------------------
// Kernel 3: per-(peak, channel) mean over length
// ---------------------------------------------------------------------------
__global__ __launch_bounds__(256)
void mean_kernel(int src, int len) {
    const float* __restrict__ in = g_buf[src];
    const int row  = blockIdx.x * 8 + (threadIdx.x >> 5);
    const int lane = threadIdx.x & 31;
    const float* p = in + (size_t)row * MAXLEN;
    float s = 0.f;
    for (int l = lane; l < len; l += 32) s += p[l];
#pragma unroll
    for (int o = 16; o; o >>= 1) s += __shfl_xor_sync(0xFFFFFFFFu, s, o);
    if (lane == 0) g_mean[row] = s / (float)len;
}

// ---------------------------------------------------------------------------
// Kernel 4: atpm head
// ---------------------------------------------------------------------------
__global__ __launch_bounds__(256)
void atpm_kernel(const float* __restrict__ w, const float* __restrict__ b,
                 float* __restrict__ out) {
    __shared__ float sh[256];
    const int n = blockIdx.x;
    const int t = threadIdx.x;
    sh[t] = g_mean[n * HID + t] * w[t];
    __syncthreads();
    for (int s = 128; s > 0; s >>= 1) {
        if (t < s) sh[t] += sh[t + s];
        __syncthreads();
    }
    if (t == 0) out[n] = softplus_f(sh[0] + b[0]);
}

// ---------------------------------------------------------------------------
// Kernel 5: profile conv (K=75, 256 -> 1) + softplus
// ---------------------------------------------------------------------------
__global__ __launch_bounds__(256)
void prof_kernel(int src, const float* __restrict__ wp,
                 const float* __restrict__ bp, float* __restrict__ out,
                 int len_in, int len_out) {
    __shared__ float hrow[512];
    __shared__ float wrow[80];
    const float* __restrict__ in = g_buf[src];
    const int n = blockIdx.x;
    const int t = threadIdx.x;
    const int l0 = t;
    const int l1 = t + 256;

    float acc0 = 0.f, acc1 = 0.f;
    for (int c = 0; c < HID; c++) {
        for (int l = t; l < len_in; l += 256)
            hrow[l] = in[((size_t)n * HID + c) * MAXLEN + l];
        if (t < PROF_K) wrow[t] = wp[c * PROF_K + t];
        __syncthreads();

#pragma unroll 5
        for (int k = 0; k < PROF_K; k++)
            acc0 = fmaf(hrow[l0 + k], wrow[k], acc0);
        if (l1 < len_out) {
#pragma unroll 5
            for (int k = 0; k < PROF_K; k++)
                acc1 = fmaf(hrow[l1 + k], wrow[k], acc1);
        }
        __syncthreads();
    }
    const float bv = bp[0];
    out[PEAKS + (size_t)n * len_out + l0] = softplus_f(acc0 + bv);
    if (l1 < len_out)
        out[PEAKS + (size_t)n * len_out + l1] = softplus_f(acc1 + bv);
}

// ---------------------------------------------------------------------------
// Launch
// ---------------------------------------------------------------------------
template <int DIL, int LEN_OUT>
static void launch_conv(int src, int layer, const float* b) {
    static bool attr_done = false;
    if (!attr_done) {
        cudaFuncSetAttribute(conv_wmma_kernel<DIL, LEN_OUT>,
                             cudaFuncAttributeMaxDynamicSharedMemorySize,
                             CONV_SMEM);
        attr_done = true;
    }
    conv_wmma_kernel<DIL, LEN_OUT>
        <<<dim3((LEN_OUT + 127) / 128, 2, PEAKS), 256, CONV_SMEM>>>(
            src, layer, b);
}

extern "C" void kernel_launch(void* const* d_in, const int* in_sizes, int n_in,
                              void* d_out, int out_size) {
    const float* x = (const float*)d_in[0];

    int iw = -1;
    for (int i = 1; i < n_in; i++)
        if (in_sizes[i] == MOTIF * HID) { iw = i; break; }

    const float* w_proj = (const float*)d_in[iw + 0];
    const float* b_proj = (const float*)d_in[iw + 1];
    const float* w_dil  = (const float*)d_in[iw + 2];
    const float* b_dil  = (const float*)d_in[iw + 3];
    const float* w_prof = (const float*)d_in[iw + 4];
    const float* b_prof = (const float*)d_in[iw + 5];
    const float* w_atpm = (const float*)d_in[iw + 6];
    const float* b_atpm = (const float*)d_in[iw + 7];
    float* out = (float*)d_out;

    // 0) pack + split conv weights
    prep_w_kernel<<<(DEPTH * HID * 768 + 255) / 256, 256>>>(w_dil);

    // 1) projection -> g_buf[0] + g_split[0]
    proj_kernel<<<dim3(GL_TOTAL / 128, HID / 128), 256>>>(x, w_proj, b_proj);

    // 2) dilated conv tower (WMMA), lengths 1000->996->...->492
    launch_conv<  2, 996>(0, 0, b_dil + 0 * HID);
    launch_conv<  4, 988>(1, 1, b_dil + 1 * HID);
    launch_conv<  8, 972>(0, 2, b_dil + 2 * HID);
    launch_conv< 16, 940>(1, 3, b_dil + 3 * HID);
    launch_conv< 32, 876>(0, 4, b_dil + 4 * HID);
    launch_conv< 64, 748>(1, 5, b_dil + 5 * HID);
    launch_conv<128, 492>(0, 6, b_dil + 6 * HID);
    const int src = 1;   // final fp32 map in g_buf[1], len = 492
    const int len = 492;

    // 3) mean over length
    mean_kernel<<<(PEAKS * HID) / 8, 256>>>(src, len);

    // 4) atpm head -> out[0..127]
    atpm_kernel<<<PEAKS, 256>>>(w_atpm, b_atpm, out);

    // 5) profile conv -> out[128 .. 128 + 128*418)
    prof_kernel<<<PEAKS, 256>>>(src, w_prof, b_prof, out, len, len - PROF_K + 1);
}

// round 12
// speedup vs baseline: 2.2086x; 1.2622x over previous
#include <cuda_runtime.h>
#include <cuda_bf16.h>
#include <mma.h>
#include <math.h>
#include <stdint.h>

using namespace nvcuda;

// ---------------------------------------------------------------------------
// Fixed problem shapes (fast path: uniform peaks)
// ---------------------------------------------------------------------------
#define BATCH      2
#define NUM_PEAKS  64
#define PEAKS      128          // BATCH * NUM_PEAKS
#define PSIZE      1000
#define MOTIF      640
#define HID        256
#define DEPTH      7
#define PROF_K     75
#define MAXLEN     1008         // padded row stride (floats)
#define GL_TOTAL   128000       // BATCH * NUM_PEAKS * PSIZE
#define BUFSZ      (PEAKS * HID * MAXLEN)

// K layout: chunks of 16 q; 2 stored blocks per operand: A=[xh|xl], B=[wh|wl]
// 3 split terms via register-fragment reuse: ah*bh + al*bh + ah*bl
#define NCHUNK     48           // conv: 768/16
#define NCHUNK_P   40           // proj: 640/16
#define CH_K       32           // stored bf16 per chunk row (2 x 16)

// smem layout (bytes): A/B stride 40 bf16 = 80B (LDSM conflict-free)
#define OP_STRIDE  40
#define A_BYTES    (128 * 80)                   // 10240
#define SM_A0      0
#define SM_A1      A_BYTES
#define SM_B0      (2 * A_BYTES)                // 20480
#define SM_B1      (3 * A_BYTES)                // 30720
#define D_LD       132                          // floats per D row (128 + 4)
#define CONV_SMEM  69632                        // D (67584) unions A/B

// ---------------------------------------------------------------------------
// Global buffers
// ---------------------------------------------------------------------------
__device__ float g_buf[2][BUFSZ + 4096];
__device__ unsigned g_split[2][BUFSZ + 4096];   // u32 = (bf16 lo<<16)|bf16 hi
__device__ __nv_bfloat16 g_wpack[DEPTH][HID][NCHUNK * CH_K];
__device__ __nv_bfloat16 g_wppack[HID][NCHUNK_P * CH_K];
__device__ float g_mean[PEAKS * HID];

__device__ __forceinline__ float softplus_f(float x) {
    return (x > 20.f) ? x : log1pf(expf(x));
}

// hi/lo bf16 split, packed into one u32 (lo<<16 | hi)
__device__ __forceinline__ unsigned pack_split(float v) {
    __nv_bfloat16 h = __float2bfloat16(v);
    __nv_bfloat16 l = __float2bfloat16(v - __bfloat162float(h));
    unsigned short hu = *(unsigned short*)&h;
    unsigned short lu = *(unsigned short*)&l;
    return ((unsigned)lu << 16) | (unsigned)hu;
}
// two floats -> bf16x2 (b in high half)
__device__ __forceinline__ unsigned pack2(float a, float b) {
    __nv_bfloat162 t = __floats2bfloat162_rn(a, b);
    return *(unsigned*)&t;
}

// cp.async helpers
__device__ __forceinline__ void cpa16(uint32_t dst, const void* src) {
    asm volatile("cp.async.ca.shared.global [%0], [%1], 16;"
                 :: "r"(dst), "l"(src));
}
__device__ __forceinline__ void cpa_commit() {
    asm volatile("cp.async.commit_group;");
}
__device__ __forceinline__ void cpa_wait0() {
    asm volatile("cp.async.wait_group 0;");
}

typedef wmma::fragment<wmma::matrix_a, 16, 16, 16, __nv_bfloat16,
                       wmma::row_major> AFrag;
typedef wmma::fragment<wmma::matrix_b, 16, 16, 16, __nv_bfloat16,
                       wmma::col_major> BFrag;
typedef wmma::fragment<wmma::accumulator, 16, 16, 16, float> CFrag;

// ---------------------------------------------------------------------------
// Kernel 0a: pack + split conv weights -> g_wpack  (chunk row: [wh|wl])
// ---------------------------------------------------------------------------
__global__ __launch_bounds__(256)
void prep_w_kernel(const float* __restrict__ w_dil) {
    int idx = blockIdx.x * 256 + threadIdx.x;
    if (idx >= DEPTH * HID * 768) return;
    int q  = idx % 768;
    int co = (idx / 768) % HID;
    int L  = idx / (768 * HID);
    int ci = q / 3, k = q - 3 * ci;
    float v = w_dil[(((size_t)L * HID + co) * HID + ci) * 3 + k];
    __nv_bfloat16 hi = __float2bfloat16(v);
    __nv_bfloat16 lo = __float2bfloat16(v - __bfloat162float(hi));
    int c = q >> 4, t = q & 15;
    __nv_bfloat16* row = &g_wpack[L][co][c * CH_K];
    row[t]      = hi;
    row[16 + t] = lo;
}

// Kernel 0b: pack + split proj weights -> g_wppack
__global__ __launch_bounds__(256)
void prep_wp_kernel(const float* __restrict__ w_proj) {
    int idx = blockIdx.x * 256 + threadIdx.x;
    if (idx >= HID * MOTIF) return;
    int m = idx % MOTIF;
    int c = idx / MOTIF;
    float v = w_proj[(size_t)c * MOTIF + m];
    __nv_bfloat16 hi = __float2bfloat16(v);
    __nv_bfloat16 lo = __float2bfloat16(v - __bfloat162float(hi));
    int ch = m >> 4, t = m & 15;
    __nv_bfloat16* row = &g_wppack[c][ch * CH_K];
    row[t]      = hi;
    row[16 + t] = lo;
}

// ---------------------------------------------------------------------------
// Shared WMMA core: given per-chunk builders, run the double-buffered loop.
// 8 warps tile M128 x N128 as 4x2 warp-tiles of 32x64.
// ---------------------------------------------------------------------------
#define WMMA_MATH(As, Bs)                                                     \
    do {                                                                      \
        AFrag ah_f[2], al_f[2];                                               \
        BFrag bh_f[4], bl_f[4];                                               \
        _Pragma("unroll")                                                     \
        for (int mi = 0; mi < 2; mi++) {                                      \
            wmma::load_matrix_sync(ah_f[mi],                                  \
                (As) + (warp_m * 32 + mi * 16) * OP_STRIDE, OP_STRIDE);       \
            wmma::load_matrix_sync(al_f[mi],                                  \
                (As) + (warp_m * 32 + mi * 16) * OP_STRIDE + 16, OP_STRIDE);  \
        }                                                                     \
        _Pragma("unroll")                                                     \
        for (int ni = 0; ni < 4; ni++) {                                      \
            wmma::load_matrix_sync(bh_f[ni],                                  \
                (Bs) + (warp_n * 64 + ni * 16) * OP_STRIDE, OP_STRIDE);       \
            wmma::load_matrix_sync(bl_f[ni],                                  \
                (Bs) + (warp_n * 64 + ni * 16) * OP_STRIDE + 16, OP_STRIDE);  \
        }                                                                     \
        _Pragma("unroll")                                                     \
        for (int mi = 0; mi < 2; mi++)                                        \
            _Pragma("unroll")                                                 \
            for (int ni = 0; ni < 4; ni++) {                                  \
                wmma::mma_sync(acc[mi][ni], ah_f[mi], bh_f[ni], acc[mi][ni]); \
                wmma::mma_sync(acc[mi][ni], al_f[mi], bh_f[ni], acc[mi][ni]); \
                wmma::mma_sync(acc[mi][ni], ah_f[mi], bl_f[ni], acc[mi][ni]); \
            }                                                                 \
    } while (0)

// ---------------------------------------------------------------------------
// Kernel 1: 1x1 motif projection via WMMA (2-block split)
// CTA = (gl-tile 128, c-half 128). A built from fp32 x (split on the fly),
// B cp.async from g_wppack.
// ---------------------------------------------------------------------------
__global__ __launch_bounds__(256, 2)
void proj_wmma_kernel(const float* __restrict__ x,
                      const float* __restrict__ bias) {
    extern __shared__ __align__(16) char smraw[];
    const uint32_t smb = (uint32_t)__cvta_generic_to_shared(smraw);

    const int tid    = threadIdx.x;
    const int wid    = tid >> 5;
    const int warp_m = wid & 3;
    const int warp_n = wid >> 2;
    const int gl0    = blockIdx.x * 128;
    const int nh     = blockIdx.y;

    const int al = tid & 127;         // gl row
    const int ah = tid >> 7;          // m half (8 dims)
    const int brow  = tid >> 1;       // c row in half
    const int bhalf = tid & 1;
    const __nv_bfloat16* wrow = &g_wppack[nh * 128 + brow][0];
    const float* xrow = x + (size_t)(gl0 + al) * MOTIF + ah * 8;

    CFrag acc[2][4];
#pragma unroll
    for (int mi = 0; mi < 2; mi++)
#pragma unroll
        for (int ni = 0; ni < 4; ni++) wmma::fill_fragment(acc[mi][ni], 0.f);

    float f[8];

    auto issue_b = [&](int c, int b) {
        const uint32_t dst = smb + (b ? SM_B1 : SM_B0) + brow * 80 + bhalf * 32;
        const __nv_bfloat16* sp = wrow + c * CH_K + bhalf * 16;
        cpa16(dst, sp);
        cpa16(dst + 16, sp + 8);
        cpa_commit();
    };
    auto a_ld = [&](int c) {
        float4 v0 = *(const float4*)(xrow + c * 16);
        float4 v1 = *(const float4*)(xrow + c * 16 + 4);
        f[0] = v0.x; f[1] = v0.y; f[2] = v0.z; f[3] = v0.w;
        f[4] = v1.x; f[5] = v1.y; f[6] = v1.z; f[7] = v1.w;
    };
    auto a_st = [&](int b) {
        float h[8], l[8];
#pragma unroll
        for (int j = 0; j < 8; j++) {
            h[j] = __bfloat162float(__float2bfloat16(f[j]));
            l[j] = f[j] - h[j];
        }
        uint4 H, L;
        H.x = pack2(h[0], h[1]); H.y = pack2(h[2], h[3]);
        H.z = pack2(h[4], h[5]); H.w = pack2(h[6], h[7]);
        L.x = pack2(l[0], l[1]); L.y = pack2(l[2], l[3]);
        L.z = pack2(l[4], l[5]); L.w = pack2(l[6], l[7]);
        const uint32_t ab = smb + (b ? SM_A1 : SM_A0) + al * 80 + ah * 16;
        asm volatile("st.shared.v4.b32 [%0], {%1, %2, %3, %4};"
            :: "r"(ab), "r"(H.x), "r"(H.y), "r"(H.z), "r"(H.w) : "memory");
        asm volatile("st.shared.v4.b32 [%0], {%1, %2, %3, %4};"
            :: "r"(ab + 32), "r"(L.x), "r"(L.y), "r"(L.z), "r"(L.w) : "memory");
    };

    issue_b(0, 0);
    a_ld(0);
    a_st(0);
    cpa_wait0();
    __syncthreads();

#pragma unroll 1
    for (int c = 0; c < NCHUNK_P; c++) {
        const int cb = c & 1;
        if (c + 1 < NCHUNK_P) { issue_b(c + 1, cb ^ 1); a_ld(c + 1); }

        const __nv_bfloat16* As =
            reinterpret_cast<const __nv_bfloat16*>(smraw + (cb ? SM_A1 : SM_A0));
        const __nv_bfloat16* Bs =
            reinterpret_cast<const __nv_bfloat16*>(smraw + (cb ? SM_B1 : SM_B0));
        WMMA_MATH(As, Bs);

        if (c + 1 < NCHUNK_P) { a_st(cb ^ 1); cpa_wait0(); }
        __syncthreads();
    }

    float* Ds = reinterpret_cast<float*>(smraw);
#pragma unroll
    for (int mi = 0; mi < 2; mi++)
#pragma unroll
        for (int ni = 0; ni < 4; ni++)
            wmma::store_matrix_sync(
                Ds + (warp_n * 64 + ni * 16) * D_LD + (warp_m * 32 + mi * 16),
                acc[mi][ni], D_LD, wmma::mem_col_major);
    __syncthreads();

#pragma unroll 1
    for (int idx = tid; idx < 128 * 128; idx += 256) {
        const int cl = idx >> 7;
        const int gi = idx & 127;
        const int gl = gl0 + gi;
        const int n  = gl / PSIZE;
        const int l  = gl - n * PSIZE;
        const int cg = nh * 128 + cl;
        const float v = Ds[cl * D_LD + gi] + bias[cg];
        const size_t off = ((size_t)n * HID + cg) * MAXLEN + l;
        g_buf[0][off]   = v;
        g_split[0][off] = pack_split(v);
    }
}

// ---------------------------------------------------------------------------
// Kernel 2: dilated conv via WMMA (2-block split + fragment reuse)
// ---------------------------------------------------------------------------
template <int DIL, int LEN_OUT>
__global__ __launch_bounds__(256, 2)
void conv_wmma_kernel(int src, int layer, const float* __restrict__ bias) {
    extern __shared__ __align__(16) char smraw[];
    const uint32_t smb = (uint32_t)__cvta_generic_to_shared(smraw);

    const int tid    = threadIdx.x;
    const int wid    = tid >> 5;
    const int warp_m = wid & 3;
    const int warp_n = wid >> 2;
    const int l0     = blockIdx.x * 128;
    const int nh     = blockIdx.y;
    const int n      = blockIdx.z;

    const unsigned* __restrict__ xsrc = g_split[src] + (size_t)n * HID * MAXLEN;
    const float* __restrict__ resbase = g_buf[src] + (size_t)n * HID * MAXLEN;
    float* __restrict__ outbase   = g_buf[src ^ 1] + (size_t)n * HID * MAXLEN;
    unsigned* __restrict__ outsplit =
        g_split[src ^ 1] + (size_t)n * HID * MAXLEN;

    const int al = tid & 127;
    const int ah = tid >> 7;
    const int brow  = tid >> 1;
    const int bhalf = tid & 1;
    const __nv_bfloat16* wrow = &g_wpack[layer][nh * 128 + brow][0];

    CFrag acc[2][4];
#pragma unroll
    for (int mi = 0; mi < 2; mi++)
#pragma unroll
        for (int ni = 0; ni < 4; ni++) wmma::fill_fragment(acc[mi][ni], 0.f);

    unsigned areg[8];

    auto issue_b = [&](int c, int b) {
        const uint32_t dst = smb + (b ? SM_B1 : SM_B0) + brow * 80 + bhalf * 32;
        const __nv_bfloat16* sp = wrow + c * CH_K + bhalf * 16;
        cpa16(dst, sp);
        cpa16(dst + 16, sp + 8);
        cpa_commit();
    };
    auto a_ld = [&](int c) {
#pragma unroll
        for (int j = 0; j < 8; j++) {
            const int q  = c * 16 + ah * 8 + j;
            const int ci = q / 3;
            const int k  = q - 3 * ci;
            areg[j] = xsrc[(size_t)ci * MAXLEN + l0 + al + k * DIL];
        }
    };
    auto a_st = [&](int b) {
        uint4 H, L;
        asm("prmt.b32 %0, %1, %2, 0x5410;" : "=r"(H.x) : "r"(areg[0]), "r"(areg[1]));
        asm("prmt.b32 %0, %1, %2, 0x5410;" : "=r"(H.y) : "r"(areg[2]), "r"(areg[3]));
        asm("prmt.b32 %0, %1, %2, 0x5410;" : "=r"(H.z) : "r"(areg[4]), "r"(areg[5]));
        asm("prmt.b32 %0, %1, %2, 0x5410;" : "=r"(H.w) : "r"(areg[6]), "r"(areg[7]));
        asm("prmt.b32 %0, %1, %2, 0x7632;" : "=r"(L.x) : "r"(areg[0]), "r"(areg[1]));
        asm("prmt.b32 %0, %1, %2, 0x7632;" : "=r"(L.y) : "r"(areg[2]), "r"(areg[3]));
        asm("prmt.b32 %0, %1, %2, 0x7632;" : "=r"(L.z) : "r"(areg[4]), "r"(areg[5]));
        asm("prmt.b32 %0, %1, %2, 0x7632;" : "=r"(L.w) : "r"(areg[6]), "r"(areg[7]));
        const uint32_t ab = smb + (b ? SM_A1 : SM_A0) + al * 80 + ah * 16;
        asm volatile("st.shared.v4.b32 [%0], {%1, %2, %3, %4};"
            :: "r"(ab), "r"(H.x), "r"(H.y), "r"(H.z), "r"(H.w) : "memory");
        asm volatile("st.shared.v4.b32 [%0], {%1, %2, %3, %4};"
            :: "r"(ab + 32), "r"(L.x), "r"(L.y), "r"(L.z), "r"(L.w) : "memory");
    };

    issue_b(0, 0);
    a_ld(0);
    a_st(0);
    cpa_wait0();
    __syncthreads();

#pragma unroll 1
    for (int c = 0; c < NCHUNK; c++) {
        const int cb = c & 1;
        if (c + 1 < NCHUNK) { issue_b(c + 1, cb ^ 1); a_ld(c + 1); }

        const __nv_bfloat16* As =
            reinterpret_cast<const __nv_bfloat16*>(smraw + (cb ? SM_A1 : SM_A0));
        const __nv_bfloat16* Bs =
            reinterpret_cast<const __nv_bfloat16*>(smraw + (cb ? SM_B1 : SM_B0));
        WMMA_MATH(As, Bs);

        if (c + 1 < NCHUNK) { a_st(cb ^ 1); cpa_wait0(); }
        __syncthreads();
    }

    float* Ds = reinterpret_cast<float*>(smraw);
#pragma unroll
    for (int mi = 0; mi < 2; mi++)
#pragma unroll
        for (int ni = 0; ni < 4; ni++)
            wmma::store_matrix_sync(
                Ds + (warp_n * 64 + ni * 16) * D_LD + (warp_m * 32 + mi * 16),
                acc[mi][ni], D_LD, wmma::mem_col_major);
    __syncthreads();

#pragma unroll 1
    for (int idx = tid; idx < 128 * 128; idx += 256) {
        const int co = idx >> 7;
        const int l  = idx & 127;
        if (l0 + l < LEN_OUT) {
            const int co_g = nh * 128 + co;
            const float d  = Ds[co * D_LD + l];
            const float v  = fmaxf(d + bias[co_g], 0.f)
                           + resbase[(size_t)co_g * MAXLEN + l0 + l + DIL];
            outbase[(size_t)co_g * MAXLEN + l0 + l]  = v;
            outsplit[(size_t)co_g * MAXLEN + l0 + l] = pack_split(v);
        }
    }
}

// ---------------------------------------------------------------------------
// Kernel 3: per-(peak, channel) mean over length
// ---------------------------------------------------------------------------
__global__ __launch_bounds__(256)
void mean_kernel(int src, int len) {
    const float* __restrict__ in = g_buf[src];
    const int row  = blockIdx.x * 8 + (threadIdx.x >> 5);
    const int lane = threadIdx.x & 31;
    const float* p = in + (size_t)row * MAXLEN;
    float s = 0.f;
    for (int l = lane; l < len; l += 32) s += p[l];
#pragma unroll
    for (int o = 16; o; o >>= 1) s += __shfl_xor_sync(0xFFFFFFFFu, s, o);
    if (lane == 0) g_mean[row] = s / (float)len;
}

// ---------------------------------------------------------------------------
// Kernel 4: atpm head
// ---------------------------------------------------------------------------
__global__ __launch_bounds__(256)
void atpm_kernel(const float* __restrict__ w, const float* __restrict__ b,
                 float* __restrict__ out) {
    __shared__ float sh[256];
    const int n = blockIdx.x;
    const int t = threadIdx.x;
    sh[t] = g_mean[n * HID + t] * w[t];
    __syncthreads();
    for (int s = 128; s > 0; s >>= 1) {
        if (t < s) sh[t] += sh[t + s];
        __syncthreads();
    }
    if (t == 0) out[n] = softplus_f(sh[0] + b[0]);
}

// ---------------------------------------------------------------------------
// Kernel 5: profile conv (K=75, 256 -> 1) + softplus
// ---------------------------------------------------------------------------
__global__ __launch_bounds__(256)
void prof_kernel(int src, const float* __restrict__ wp,
                 const float* __restrict__ bp, float* __restrict__ out,
                 int len_in, int len_out) {
    __shared__ float hrow[512];
    __shared__ float wrow[80];
    const float* __restrict__ in = g_buf[src];
    const int n = blockIdx.x;
    const int t = threadIdx.x;
    const int l0 = t;
    const int l1 = t + 256;

    float acc0 = 0.f, acc1 = 0.f;
    for (int c = 0; c < HID; c++) {
        for (int l = t; l < len_in; l += 256)
            hrow[l] = in[((size_t)n * HID + c) * MAXLEN + l];
        if (t < PROF_K) wrow[t] = wp[c * PROF_K + t];
        __syncthreads();

#pragma unroll 5
        for (int k = 0; k < PROF_K; k++)
            acc0 = fmaf(hrow[l0 + k], wrow[k], acc0);
        if (l1 < len_out) {
#pragma unroll 5
            for (int k = 0; k < PROF_K; k++)
                acc1 = fmaf(hrow[l1 + k], wrow[k], acc1);
        }
        __syncthreads();
    }
    const float bv = bp[0];
    out[PEAKS + (size_t)n * len_out + l0] = softplus_f(acc0 + bv);
    if (l1 < len_out)
        out[PEAKS + (size_t)n * len_out + l1] = softplus_f(acc1 + bv);
}

// ---------------------------------------------------------------------------
// Launch
// ---------------------------------------------------------------------------
template <int DIL, int LEN_OUT>
static void launch_conv(int src, int layer, const float* b) {
    static bool attr_done = false;
    if (!attr_done) {
        cudaFuncSetAttribute(conv_wmma_kernel<DIL, LEN_OUT>,
                             cudaFuncAttributeMaxDynamicSharedMemorySize,
                             CONV_SMEM);
        attr_done = true;
    }
    conv_wmma_kernel<DIL, LEN_OUT>
        <<<dim3((LEN_OUT + 127) / 128, 2, PEAKS), 256, CONV_SMEM>>>(
            src, layer, b);
}

extern "C" void kernel_launch(void* const* d_in, const int* in_sizes, int n_in,
                              void* d_out, int out_size) {
    const float* x = (const float*)d_in[0];

    int iw = -1;
    for (int i = 1; i < n_in; i++)
        if (in_sizes[i] == MOTIF * HID) { iw = i; break; }

    const float* w_proj = (const float*)d_in[iw + 0];
    const float* b_proj = (const float*)d_in[iw + 1];
    const float* w_dil  = (const float*)d_in[iw + 2];
    const float* b_dil  = (const float*)d_in[iw + 3];
    const float* w_prof = (const float*)d_in[iw + 4];
    const float* b_prof = (const float*)d_in[iw + 5];
    const float* w_atpm = (const float*)d_in[iw + 6];
    const float* b_atpm = (const float*)d_in[iw + 7];
    float* out = (float*)d_out;

    static bool proj_attr = false;
    if (!proj_attr) {
        cudaFuncSetAttribute(proj_wmma_kernel,
                             cudaFuncAttributeMaxDynamicSharedMemorySize,
                             CONV_SMEM);
        proj_attr = true;
    }

    // 0) pack + split weights
    prep_w_kernel<<<(DEPTH * HID * 768 + 255) / 256, 256>>>(w_dil);
    prep_wp_kernel<<<(HID * MOTIF + 255) / 256, 256>>>(w_proj);

    // 1) projection (WMMA) -> g_buf[0] + g_split[0]
    proj_wmma_kernel<<<dim3(GL_TOTAL / 128, 2, 1), 256, CONV_SMEM>>>(x, b_proj);

    // 2) dilated conv tower (WMMA), lengths 1000->996->...->492
    launch_conv<  2, 996>(0, 0, b_dil + 0 * HID);
    launch_conv<  4, 988>(1, 1, b_dil + 1 * HID);
    launch_conv<  8, 972>(0, 2, b_dil + 2 * HID);
    launch_conv< 16, 940>(1, 3, b_dil + 3 * HID);
    launch_conv< 32, 876>(0, 4, b_dil + 4 * HID);
    launch_conv< 64, 748>(1, 5, b_dil + 5 * HID);
    launch_conv<128, 492>(0, 6, b_dil + 6 * HID);
    const int src = 1;   // final fp32 map in g_buf[1], len = 492
    const int len = 492;

    // 3) mean over length
    mean_kernel<<<(PEAKS * HID) / 8, 256>>>(src, len);

    // 4) atpm head -> out[0..127]
    atpm_kernel<<<PEAKS, 256>>>(w_atpm, b_atpm, out);

    // 5) profile conv -> out[128 .. 128 + 128*418)
    prof_kernel<<<PEAKS, 256>>>(src, w_prof, b_prof, out, len, len - PROF_K + 1);
}

// round 16
// speedup vs baseline: 2.2251x; 1.0074x over previous
#include <cuda_runtime.h>
#include <cuda_bf16.h>
#include <mma.h>
#include <math.h>
#include <stdint.h>

using namespace nvcuda;

// ---------------------------------------------------------------------------
// Fixed problem shapes (fast path: uniform peaks)
// ---------------------------------------------------------------------------
#define BATCH      2
#define NUM_PEAKS  64
#define PEAKS      128          // BATCH * NUM_PEAKS
#define PSIZE      1000
#define MOTIF      640
#define HID        256
#define DEPTH      7
#define PROF_K     75
#define MAXLEN     1008         // padded row stride (floats)
#define GL_TOTAL   128000       // BATCH * NUM_PEAKS * PSIZE
#define BUFSZ      (PEAKS * HID * MAXLEN)

// K layout: 16-q packed chunks, 2 stored blocks per operand [hi|lo] (32 bf16)
#define NCHUNK16   48           // conv 16-q chunks (768/16)
#define NCHUNK_P   40           // proj 16-q chunks (640/16)
#define NITER      24           // conv iterations (2 chunks each)
#define CH_K       32           // stored bf16 per 16-q chunk row

// conv smem: rows of 64 bf16 (2 sub-chunks), stride 72 bf16 = 144 B
#define C_STRIDE   72
#define C_AB       (128 * 144)                  // 18432
#define C_A0       0
#define C_A1       C_AB
#define C_B0       (2 * C_AB)
#define C_B1       (3 * C_AB)
#define CONV_SMEM  (4 * C_AB)                   // 73728 (D 67584 unions)

// proj smem: rows of 32 bf16, stride 40 bf16 = 80 B (unchanged R12)
#define P_STRIDE   40
#define P_AB       (128 * 80)                   // 10240
#define P_A0       0
#define P_A1       P_AB
#define P_B0       (2 * P_AB)
#define P_B1       (3 * P_AB)
#define PROJ_SMEM  69632                        // D unions

#define D_LD       132                          // floats per D row

// ---------------------------------------------------------------------------
// Global buffers
// ---------------------------------------------------------------------------
__device__ float g_buf[2][BUFSZ + 4096];
__device__ unsigned g_split[2][BUFSZ + 4096];   // u32 = (bf16 lo<<16)|bf16 hi
__device__ __nv_bfloat16 g_wpack[DEPTH][HID][NCHUNK16 * CH_K];
__device__ __nv_bfloat16 g_wppack[HID][NCHUNK_P * CH_K];
__device__ float g_mean[PEAKS * HID];

__device__ __forceinline__ float softplus_f(float x) {
    return (x > 20.f) ? x : log1pf(expf(x));
}
__device__ __forceinline__ unsigned pack_split(float v) {
    __nv_bfloat16 h = __float2bfloat16(v);
    __nv_bfloat16 l = __float2bfloat16(v - __bfloat162float(h));
    unsigned short hu = *(unsigned short*)&h;
    unsigned short lu = *(unsigned short*)&l;
    return ((unsigned)lu << 16) | (unsigned)hu;
}
__device__ __forceinline__ unsigned pack2(float a, float b) {
    __nv_bfloat162 t = __floats2bfloat162_rn(a, b);
    return *(unsigned*)&t;
}
__device__ __forceinline__ void cpa16(uint32_t dst, const void* src) {
    asm volatile("cp.async.ca.shared.global [%0], [%1], 16;"
                 :: "r"(dst), "l"(src));
}
__device__ __forceinline__ void cpa_commit() {
    asm volatile("cp.async.commit_group;");
}
__device__ __forceinline__ void cpa_wait0() {
    asm volatile("cp.async.wait_group 0;");
}

typedef wmma::fragment<wmma::matrix_a, 16, 16, 16, __nv_bfloat16,
                       wmma::row_major> AFrag;
typedef wmma::fragment<wmma::matrix_b, 16, 16, 16, __nv_bfloat16,
                       wmma::col_major> BFrag;
typedef wmma::fragment<wmma::accumulator, 16, 16, 16, float> CFrag;

// Phased 3-term split math on one 16-q block at column offset COFF.
// Load order hh -> lh -> hl keeps at most 10 fragments live.
#define WMMA_MATH_S(As, Bs, STRIDE, COFF)                                     \
    do {                                                                      \
        AFrag ahf[2], alf[2];                                                 \
        BFrag bhf[4], blf[4];                                                 \
        _Pragma("unroll")                                                     \
        for (int mi = 0; mi < 2; mi++)                                        \
            wmma::load_matrix_sync(ahf[mi],                                   \
                (As) + (warp_m * 32 + mi * 16) * (STRIDE) + (COFF), (STRIDE));\
        _Pragma("unroll")                                                     \
        for (int ni = 0; ni < 4; ni++)                                        \
            wmma::load_matrix_sync(bhf[ni],                                   \
                (Bs) + (warp_n * 64 + ni * 16) * (STRIDE) + (COFF), (STRIDE));\
        _Pragma("unroll")                                                     \
        for (int mi = 0; mi < 2; mi++)                                        \
            _Pragma("unroll")                                                 \
            for (int ni = 0; ni < 4; ni++)                                    \
                wmma::mma_sync(acc[mi][ni], ahf[mi], bhf[ni], acc[mi][ni]);   \
        _Pragma("unroll")                                                     \
        for (int mi = 0; mi < 2; mi++)                                        \
            wmma::load_matrix_sync(alf[mi],                                   \
                (As) + (warp_m * 32 + mi * 16) * (STRIDE) + (COFF) + 16,      \
                (STRIDE));                                                    \
        _Pragma("unroll")                                                     \
        for (int mi = 0; mi < 2; mi++)                                        \
            _Pragma("unroll")                                                 \
            for (int ni = 0; ni < 4; ni++)                                    \
                wmma::mma_sync(acc[mi][ni], alf[mi], bhf[ni], acc[mi][ni]);   \
        _Pragma("unroll")                                                     \
        for (int ni = 0; ni < 4; ni++)                                        \
            wmma::load_matrix_sync(blf[ni],                                   \
                (Bs) + (warp_n * 64 + ni * 16) * (STRIDE) + (COFF) + 16,      \
                (STRIDE));                                                    \
        _Pragma("unroll")                                                     \
        for (int mi = 0; mi < 2; mi++)                                        \
            _Pragma("unroll")                                                 \
            for (int ni = 0; ni < 4; ni++)                                    \
                wmma::mma_sync(acc[mi][ni], ahf[mi], blf[ni], acc[mi][ni]);   \
    } while (0)

// ---------------------------------------------------------------------------
// Kernel 0a/0b: pack + split weights (chunk row: [wh(16)|wl(16)])
// ---------------------------------------------------------------------------
__global__ __launch_bounds__(256)
void prep_w_kernel(const float* __restrict__ w_dil) {
    int idx = blockIdx.x * 256 + threadIdx.x;
    if (idx >= DEPTH * HID * 768) return;
    int q  = idx % 768;
    int co = (idx / 768) % HID;
    int L  = idx / (768 * HID);
    int ci = q / 3, k = q - 3 * ci;
    float v = w_dil[(((size_t)L * HID + co) * HID + ci) * 3 + k];
    __nv_bfloat16 hi = __float2bfloat16(v);
    __nv_bfloat16 lo = __float2bfloat16(v - __bfloat162float(hi));
    int c = q >> 4, t = q & 15;
    __nv_bfloat16* row = &g_wpack[L][co][c * CH_K];
    row[t]      = hi;
    row[16 + t] = lo;
}

__global__ __launch_bounds__(256)
void prep_wp_kernel(const float* __restrict__ w_proj) {
    int idx = blockIdx.x * 256 + threadIdx.x;
    if (idx >= HID * MOTIF) return;
    int m = idx % MOTIF;
    int c = idx / MOTIF;
    float v = w_proj[(size_t)c * MOTIF + m];
    __nv_bfloat16 hi = __float2bfloat16(v);
    __nv_bfloat16 lo = __float2bfloat16(v - __bfloat162float(hi));
    int ch = m >> 4, t = m & 15;
    __nv_bfloat16* row = &g_wppack[c][ch * CH_K];
    row[t]      = hi;
    row[16 + t] = lo;
}

// ---------------------------------------------------------------------------
// Kernel 1: 1x1 motif projection via WMMA (unchanged from R12)
// ---------------------------------------------------------------------------
__global__ __launch_bounds__(256, 2)
void proj_wmma_kernel(const float* __restrict__ x,
                      const float* __restrict__ bias) {
    extern __shared__ __align__(16) char smraw[];
    const uint32_t smb = (uint32_t)__cvta_generic_to_shared(smraw);

    const int tid    = threadIdx.x;
    const int wid    = tid >> 5;
    const int warp_m = wid & 3;
    const int warp_n = wid >> 2;
    const int gl0    = blockIdx.x * 128;
    const int nh     = blockIdx.y;

    const int al = tid & 127;
    const int ah = tid >> 7;
    const int brow  = tid >> 1;
    const int bhalf = tid & 1;
    const __nv_bfloat16* wrow = &g_wppack[nh * 128 + brow][0];
    const float* xrow = x + (size_t)(gl0 + al) * MOTIF + ah * 8;

    CFrag acc[2][4];
#pragma unroll
    for (int mi = 0; mi < 2; mi++)
#pragma unroll
        for (int ni = 0; ni < 4; ni++) wmma::fill_fragment(acc[mi][ni], 0.f);

    float f[8];

    auto issue_b = [&](int c, int b) {
        const uint32_t dst = smb + (b ? P_B1 : P_B0) + brow * 80 + bhalf * 32;
        const __nv_bfloat16* sp = wrow + c * CH_K + bhalf * 16;
        cpa16(dst, sp);
        cpa16(dst + 16, sp + 8);
        cpa_commit();
    };
    auto a_ld = [&](int c) {
        float4 v0 = *(const float4*)(xrow + c * 16);
        float4 v1 = *(const float4*)(xrow + c * 16 + 4);
        f[0] = v0.x; f[1] = v0.y; f[2] = v0.z; f[3] = v0.w;
        f[4] = v1.x; f[5] = v1.y; f[6] = v1.z; f[7] = v1.w;
    };
    auto a_st = [&](int b) {
        float h[8], l[8];
#pragma unroll
        for (int j = 0; j < 8; j++) {
            h[j] = __bfloat162float(__float2bfloat16(f[j]));
            l[j] = f[j] - h[j];
        }
        uint4 H, L;
        H.x = pack2(h[0], h[1]); H.y = pack2(h[2], h[3]);
        H.z = pack2(h[4], h[5]); H.w = pack2(h[6], h[7]);
        L.x = pack2(l[0], l[1]); L.y = pack2(l[2], l[3]);
        L.z = pack2(l[4], l[5]); L.w = pack2(l[6], l[7]);
        const uint32_t ab = smb + (b ? P_A1 : P_A0) + al * 80 + ah * 16;
        asm volatile("st.shared.v4.b32 [%0], {%1, %2, %3, %4};"
            :: "r"(ab), "r"(H.x), "r"(H.y), "r"(H.z), "r"(H.w) : "memory");
        asm volatile("st.shared.v4.b32 [%0], {%1, %2, %3, %4};"
            :: "r"(ab + 32), "r"(L.x), "r"(L.y), "r"(L.z), "r"(L.w) : "memory");
    };

    issue_b(0, 0);
    a_ld(0);
    a_st(0);
    cpa_wait0();
    __syncthreads();

#pragma unroll 1
    for (int c = 0; c < NCHUNK_P; c++) {
        const int cb = c & 1;
        if (c + 1 < NCHUNK_P) { issue_b(c + 1, cb ^ 1); a_ld(c + 1); }

        const __nv_bfloat16* As =
            reinterpret_cast<const __nv_bfloat16*>(smraw + (cb ? P_A1 : P_A0));
        const __nv_bfloat16* Bs =
            reinterpret_cast<const __nv_bfloat16*>(smraw + (cb ? P_B1 : P_B0));
        WMMA_MATH_S(As, Bs, P_STRIDE, 0);

        if (c + 1 < NCHUNK_P) { a_st(cb ^ 1); cpa_wait0(); }
        __syncthreads();
    }

    float* Ds = reinterpret_cast<float*>(smraw);
#pragma unroll
    for (int mi = 0; mi < 2; mi++)
#pragma unroll
        for (int ni = 0; ni < 4; ni++)
            wmma::store_matrix_sync(
                Ds + (warp_n * 64 + ni * 16) * D_LD + (warp_m * 32 + mi * 16),
                acc[mi][ni], D_LD, wmma::mem_col_major);
    __syncthreads();

#pragma unroll 1
    for (int idx = tid; idx < 128 * 128; idx += 256) {
        const int cl = idx >> 7;
        const int gi = idx & 127;
        const int gl = gl0 + gi;
        const int n  = gl / PSIZE;
        const int l  = gl - n * PSIZE;
        const int cg = nh * 128 + cl;
        const float v = Ds[cl * D_LD + gi] + bias[cg];
        const size_t off = ((size_t)n * HID + cg) * MAXLEN + l;
        g_buf[0][off]   = v;
        g_split[0][off] = pack_split(v);
    }
}

// ---------------------------------------------------------------------------
// Kernel 2: dilated conv via WMMA, 32-q iterations (2 sub-chunks), half the
// syncs of R12. Thread (row al, half ah) owns sub-chunk ah of each iteration;
// builder stores split into two 8-value halves interleaved with the math.
// ---------------------------------------------------------------------------
template <int DIL, int LEN_OUT>
__global__ __launch_bounds__(256, 2)
void conv_wmma_kernel(int src, int layer, const float* __restrict__ bias) {
    extern __shared__ __align__(16) char smraw[];
    const uint32_t smb = (uint32_t)__cvta_generic_to_shared(smraw);

    const int tid    = threadIdx.x;
    const int wid    = tid >> 5;
    const int warp_m = wid & 3;
    const int warp_n = wid >> 2;
    const int l0     = blockIdx.x * 128;
    const int nh     = blockIdx.y;
    const int n      = blockIdx.z;

    const unsigned* __restrict__ xsrc = g_split[src] + (size_t)n * HID * MAXLEN;
    const float* __restrict__ resbase = g_buf[src] + (size_t)n * HID * MAXLEN;
    float* __restrict__ outbase   = g_buf[src ^ 1] + (size_t)n * HID * MAXLEN;
    unsigned* __restrict__ outsplit =
        g_split[src ^ 1] + (size_t)n * HID * MAXLEN;

    const int al = tid & 127;          // A row (l)
    const int ah = tid >> 7;           // sub-chunk owner (0/1)
    const int brow  = tid >> 1;        // B row (co in half)
    const int bhalf = tid & 1;         // 64B half of the 128B B row
    const __nv_bfloat16* wrow = &g_wpack[layer][nh * 128 + brow][0];

    CFrag acc[2][4];
#pragma unroll
    for (int mi = 0; mi < 2; mi++)
#pragma unroll
        for (int ni = 0; ni < 4; ni++) wmma::fill_fragment(acc[mi][ni], 0.f);

    unsigned areg[16];

    // B: iteration it uses packed chunks 2it, 2it+1 = 64 contiguous bf16
    auto issue_b = [&](int it, int b) {
        const uint32_t dst =
            smb + (b ? C_B1 : C_B0) + brow * 144 + bhalf * 64;
        const __nv_bfloat16* sp = wrow + it * 64 + bhalf * 32;
        cpa16(dst,      sp);
        cpa16(dst + 16, sp + 8);
        cpa16(dst + 32, sp + 16);
        cpa16(dst + 48, sp + 24);
        cpa_commit();
    };
    // A: thread owns 16 q of its sub-chunk: q = it*32 + ah*16 + j
    auto a_ld = [&](int it) {
#pragma unroll
        for (int j = 0; j < 16; j++) {
            const int q  = it * 32 + ah * 16 + j;
            const int ci = q / 3;
            const int k  = q - 3 * ci;
            areg[j] = xsrc[(size_t)ci * MAXLEN + l0 + al + k * DIL];
        }
    };
    // store half h (values 8h..8h+7): H -> col bytes ah*64 + h*16,
    // L -> ah*64 + 32 + h*16
    auto a_st_half = [&](int b, int h) {
        const unsigned* a = areg + h * 8;
        uint4 H, L;
        asm("prmt.b32 %0, %1, %2, 0x5410;" : "=r"(H.x) : "r"(a[0]), "r"(a[1]));
        asm("prmt.b32 %0, %1, %2, 0x5410;" : "=r"(H.y) : "r"(a[2]), "r"(a[3]));
        asm("prmt.b32 %0, %1, %2, 0x5410;" : "=r"(H.z) : "r"(a[4]), "r"(a[5]));
        asm("prmt.b32 %0, %1, %2, 0x5410;" : "=r"(H.w) : "r"(a[6]), "r"(a[7]));
        asm("prmt.b32 %0, %1, %2, 0x7632;" : "=r"(L.x) : "r"(a[0]), "r"(a[1]));
        asm("prmt.b32 %0, %1, %2, 0x7632;" : "=r"(L.y) : "r"(a[2]), "r"(a[3]));
        asm("prmt.b32 %0, %1, %2, 0x7632;" : "=r"(L.z) : "r"(a[4]), "r"(a[5]));
        asm("prmt.b32 %0, %1, %2, 0x7632;" : "=r"(L.w) : "r"(a[6]), "r"(a[7]));
        const uint32_t ab =
            smb + (b ? C_A1 : C_A0) + al * 144 + ah * 64 + h * 16;
        asm volatile("st.shared.v4.b32 [%0], {%1, %2, %3, %4};"
            :: "r"(ab), "r"(H.x), "r"(H.y), "r"(H.z), "r"(H.w) : "memory");
        asm volatile("st.shared.v4.b32 [%0], {%1, %2, %3, %4};"
            :: "r"(ab + 32), "r"(L.x), "r"(L.y), "r"(L.z), "r"(L.w) : "memory");
    };

    // prologue: iteration 0
    issue_b(0, 0);
    a_ld(0);
    a_st_half(0, 0);
    a_st_half(0, 1);
    cpa_wait0();
    __syncthreads();

#pragma unroll 1
    for (int c = 0; c < NITER; c++) {
        const int cb = c & 1;
        if (c + 1 < NITER) { issue_b(c + 1, cb ^ 1); a_ld(c + 1); }

        const __nv_bfloat16* As =
            reinterpret_cast<const __nv_bfloat16*>(smraw + (cb ? C_A1 : C_A0));
        const __nv_bfloat16* Bs =
            reinterpret_cast<const __nv_bfloat16*>(smraw + (cb ? C_B1 : C_B0));

        WMMA_MATH_S(As, Bs, C_STRIDE, 0);        // sub-chunk 0
        if (c + 1 < NITER) a_st_half(cb ^ 1, 0); // free areg[0..7]
        WMMA_MATH_S(As, Bs, C_STRIDE, 32);       // sub-chunk 1
        if (c + 1 < NITER) { a_st_half(cb ^ 1, 1); cpa_wait0(); }
        __syncthreads();
    }

    // epilogue: acc -> smem D [co][l], then fused bias+relu+residual out
    float* Ds = reinterpret_cast<float*>(smraw);
#pragma unroll
    for (int mi = 0; mi < 2; mi++)
#pragma unroll
        for (int ni = 0; ni < 4; ni++)
            wmma::store_matrix_sync(
                Ds + (warp_n * 64 + ni * 16) * D_LD + (warp_m * 32 + mi * 16),
                acc[mi][ni], D_LD, wmma::mem_col_major);
    __syncthreads();

#pragma unroll 1
    for (int idx = tid; idx < 128 * 128; idx += 256) {
        const int co = idx >> 7;
        const int l  = idx & 127;
        if (l0 + l < LEN_OUT) {
            const int co_g = nh * 128 + co;
            const float d  = Ds[co * D_LD + l];
            const float v  = fmaxf(d + bias[co_g], 0.f)
                           + resbase[(size_t)co_g * MAXLEN + l0 + l + DIL];
            outbase[(size_t)co_g * MAXLEN + l0 + l]  = v;
            outsplit[(size_t)co_g * MAXLEN + l0 + l] = pack_split(v);
        }
    }
}

// ---------------------------------------------------------------------------
// Kernel 3: per-(peak, channel) mean over length
// ---------------------------------------------------------------------------
__global__ __launch_bounds__(256)
void mean_kernel(int src, int len) {
    const float* __restrict__ in = g_buf[src];
    const int row  = blockIdx.x * 8 + (threadIdx.x >> 5);
    const int lane = threadIdx.x & 31;
    const float* p = in + (size_t)row * MAXLEN;
    float s = 0.f;
    for (int l = lane; l < len; l += 32) s += p[l];
#pragma unroll
    for (int o = 16; o; o >>= 1) s += __shfl_xor_sync(0xFFFFFFFFu, s, o);
    if (lane == 0) g_mean[row] = s / (float)len;
}

// ---------------------------------------------------------------------------
// Kernel 4: atpm head
// ---------------------------------------------------------------------------
__global__ __launch_bounds__(256)
void atpm_kernel(const float* __restrict__ w, const float* __restrict__ b,
                 float* __restrict__ out) {
    __shared__ float sh[256];
    const int n = blockIdx.x;
    const int t = threadIdx.x;
    sh[t] = g_mean[n * HID + t] * w[t];
    __syncthreads();
    for (int s = 128; s > 0; s >>= 1) {
        if (t < s) sh[t] += sh[t + s];
        __syncthreads();
    }
    if (t == 0) out[n] = softplus_f(sh[0] + b[0]);
}

// ---------------------------------------------------------------------------
// Kernel 5: profile conv (K=75, 256 -> 1) + softplus
// ---------------------------------------------------------------------------
__global__ __launch_bounds__(256)
void prof_kernel(int src, const float* __restrict__ wp,
                 const float* __restrict__ bp, float* __restrict__ out,
                 int len_in, int len_out) {
    __shared__ float hrow[512];
    __shared__ float wrow[80];
    const float* __restrict__ in = g_buf[src];
    const int n = blockIdx.x;
    const int t = threadIdx.x;
    const int l0 = t;
    const int l1 = t + 256;

    float acc0 = 0.f, acc1 = 0.f;
    for (int c = 0; c < HID; c++) {
        for (int l = t; l < len_in; l += 256)
            hrow[l] = in[((size_t)n * HID + c) * MAXLEN + l];
        if (t < PROF_K) wrow[t] = wp[c * PROF_K + t];
        __syncthreads();

#pragma unroll 5
        for (int k = 0; k < PROF_K; k++)
            acc0 = fmaf(hrow[l0 + k], wrow[k], acc0);
        if (l1 < len_out) {
#pragma unroll 5
            for (int k = 0; k < PROF_K; k++)
                acc1 = fmaf(hrow[l1 + k], wrow[k], acc1);
        }
        __syncthreads();
    }
    const float bv = bp[0];
    out[PEAKS + (size_t)n * len_out + l0] = softplus_f(acc0 + bv);
    if (l1 < len_out)
        out[PEAKS + (size_t)n * len_out + l1] = softplus_f(acc1 + bv);
}

// ---------------------------------------------------------------------------
// Launch
// ---------------------------------------------------------------------------
template <int DIL, int LEN_OUT>
static void launch_conv(int src, int layer, const float* b) {
    static bool attr_done = false;
    if (!attr_done) {
        cudaFuncSetAttribute(conv_wmma_kernel<DIL, LEN_OUT>,
                             cudaFuncAttributeMaxDynamicSharedMemorySize,
                             CONV_SMEM);
        attr_done = true;
    }
    conv_wmma_kernel<DIL, LEN_OUT>
        <<<dim3((LEN_OUT + 127) / 128, 2, PEAKS), 256, CONV_SMEM>>>(
            src, layer, b);
}

extern "C" void kernel_launch(void* const* d_in, const int* in_sizes, int n_in,
                              void* d_out, int out_size) {
    const float* x = (const float*)d_in[0];

    int iw = -1;
    for (int i = 1; i < n_in; i++)
        if (in_sizes[i] == MOTIF * HID) { iw = i; break; }

    const float* w_proj = (const float*)d_in[iw + 0];
    const float* b_proj = (const float*)d_in[iw + 1];
    const float* w_dil  = (const float*)d_in[iw + 2];
    const float* b_dil  = (const float*)d_in[iw + 3];
    const float* w_prof = (const float*)d_in[iw + 4];
    const float* b_prof = (const float*)d_in[iw + 5];
    const float* w_atpm = (const float*)d_in[iw + 6];
    const float* b_atpm = (const float*)d_in[iw + 7];
    float* out = (float*)d_out;

    static bool proj_attr = false;
    if (!proj_attr) {
        cudaFuncSetAttribute(proj_wmma_kernel,
                             cudaFuncAttributeMaxDynamicSharedMemorySize,
                             PROJ_SMEM);
        proj_attr = true;
    }

    // 0) pack + split weights
    prep_w_kernel<<<(DEPTH * HID * 768 + 255) / 256, 256>>>(w_dil);
    prep_wp_kernel<<<(HID * MOTIF + 255) / 256, 256>>>(w_proj);

    // 1) projection (WMMA) -> g_buf[0] + g_split[0]
    proj_wmma_kernel<<<dim3(GL_TOTAL / 128, 2, 1), 256, PROJ_SMEM>>>(x, b_proj);

    // 2) dilated conv tower (WMMA), lengths 1000->996->...->492
    launch_conv<  2, 996>(0, 0, b_dil + 0 * HID);
    launch_conv<  4, 988>(1, 1, b_dil + 1 * HID);
    launch_conv<  8, 972>(0, 2, b_dil + 2 * HID);
    launch_conv< 16, 940>(1, 3, b_dil + 3 * HID);
    launch_conv< 32, 876>(0, 4, b_dil + 4 * HID);
    launch_conv< 64, 748>(1, 5, b_dil + 5 * HID);
    launch_conv<128, 492>(0, 6, b_dil + 6 * HID);
    const int src = 1;   // final fp32 map in g_buf[1], len = 492
    const int len = 492;

    // 3) mean over length
    mean_kernel<<<(PEAKS * HID) / 8, 256>>>(src, len);

    // 4) atpm head -> out[0..127]
    atpm_kernel<<<PEAKS, 256>>>(w_atpm, b_atpm, out);

    // 5) profile conv -> out[128 .. 128 + 128*418)
    prof_kernel<<<PEAKS, 256>>>(src, w_prof, b_prof, out, len, len - PROF_K + 1);
}

// round 17
// speedup vs baseline: 2.2920x; 1.0301x over previous
#include <cuda_runtime.h>
#include <cuda_bf16.h>
#include <mma.h>
#include <math.h>
#include <stdint.h>

using namespace nvcuda;

// ---------------------------------------------------------------------------
// Fixed problem shapes (fast path: uniform peaks)
// ---------------------------------------------------------------------------
#define BATCH      2
#define NUM_PEAKS  64
#define PEAKS      128          // BATCH * NUM_PEAKS
#define PSIZE      1000
#define MOTIF      640
#define HID        256
#define DEPTH      7
#define PROF_K     75
#define MAXLEN     1008         // padded row stride (floats)
#define GL_TOTAL   128000       // BATCH * NUM_PEAKS * PSIZE
#define BUFSZ      (PEAKS * HID * MAXLEN)

// K layout: 16-q packed chunks, 2 stored blocks per operand [hi|lo] (32 bf16)
#define NCHUNK16   48           // conv 16-q chunks (768/16)
#define NCHUNK_P   40           // proj 16-q chunks (640/16)
#define CH_K       32           // stored bf16 per 16-q chunk row

// common smem row: 32 bf16 payload, stride 40 bf16 = 80 B (conflict-free)
#define OP_STRIDE  40

// conv smem (CTA tile 128l x 64co): A 128x80B, B 64x80B, double-buffered
#define CV_A       10240
#define CV_B       5120
#define CV_A0      0
#define CV_A1      CV_A
#define CV_B0      (2 * CV_A)                   // 20480
#define CV_B1      (2 * CV_A + CV_B)            // 25600
#define CONV_SMEM  34816                        // D (64*132*4=33792) unions

// proj smem (CTA tile 128gl x 128c): unchanged proven R12 layout
#define P_AB       (128 * 80)                   // 10240
#define P_A0       0
#define P_A1       P_AB
#define P_B0       (2 * P_AB)
#define P_B1       (3 * P_AB)
#define PROJ_SMEM  69632                        // D unions

#define D_LD       132                          // floats per D row

// ---------------------------------------------------------------------------
// Global buffers
// ---------------------------------------------------------------------------
__device__ float g_buf[2][BUFSZ + 4096];
__device__ unsigned g_split[2][BUFSZ + 4096];   // u32 = (bf16 lo<<16)|bf16 hi
__device__ __nv_bfloat16 g_wpack[DEPTH][HID][NCHUNK16 * CH_K];
__device__ __nv_bfloat16 g_wppack[HID][NCHUNK_P * CH_K];
__device__ float g_mean[PEAKS * HID];

__device__ __forceinline__ float softplus_f(float x) {
    return (x > 20.f) ? x : log1pf(expf(x));
}
__device__ __forceinline__ unsigned pack_split(float v) {
    __nv_bfloat16 h = __float2bfloat16(v);
    __nv_bfloat16 l = __float2bfloat16(v - __bfloat162float(h));
    unsigned short hu = *(unsigned short*)&h;
    unsigned short lu = *(unsigned short*)&l;
    return ((unsigned)lu << 16) | (unsigned)hu;
}
__device__ __forceinline__ unsigned pack2(float a, float b) {
    __nv_bfloat162 t = __floats2bfloat162_rn(a, b);
    return *(unsigned*)&t;
}
__device__ __forceinline__ void cpa16(uint32_t dst, const void* src) {
    asm volatile("cp.async.ca.shared.global [%0], [%1], 16;"
                 :: "r"(dst), "l"(src));
}
__device__ __forceinline__ void cpa_commit() {
    asm volatile("cp.async.commit_group;");
}
__device__ __forceinline__ void cpa_wait0() {
    asm volatile("cp.async.wait_group 0;");
}

typedef wmma::fragment<wmma::matrix_a, 16, 16, 16, __nv_bfloat16,
                       wmma::row_major> AFrag;
typedef wmma::fragment<wmma::matrix_b, 16, 16, 16, __nv_bfloat16,
                       wmma::col_major> BFrag;
typedef wmma::fragment<wmma::accumulator, 16, 16, 16, float> CFrag;

// 3-term split math, warp tile 32x64 (proj): acc[2][4]
#define WMMA_MATH_S(As, Bs, STRIDE, COFF)                                     \
    do {                                                                      \
        AFrag ahf[2], alf[2];                                                 \
        BFrag bhf[4], blf[4];                                                 \
        _Pragma("unroll")                                                     \
        for (int mi = 0; mi < 2; mi++)                                        \
            wmma::load_matrix_sync(ahf[mi],                                   \
                (As) + (warp_m * 32 + mi * 16) * (STRIDE) + (COFF), (STRIDE));\
        _Pragma("unroll")                                                     \
        for (int ni = 0; ni < 4; ni++)                                        \
            wmma::load_matrix_sync(bhf[ni],                                   \
                (Bs) + (warp_n * 64 + ni * 16) * (STRIDE) + (COFF), (STRIDE));\
        _Pragma("unroll")                                                     \
        for (int mi = 0; mi < 2; mi++)                                        \
            _Pragma("unroll")                                                 \
            for (int ni = 0; ni < 4; ni++)                                    \
                wmma::mma_sync(acc[mi][ni], ahf[mi], bhf[ni], acc[mi][ni]);   \
        _Pragma("unroll")                                                     \
        for (int mi = 0; mi < 2; mi++)                                        \
            wmma::load_matrix_sync(alf[mi],                                   \
                (As) + (warp_m * 32 + mi * 16) * (STRIDE) + (COFF) + 16,      \
                (STRIDE));                                                    \
        _Pragma("unroll")                                                     \
        for (int mi = 0; mi < 2; mi++)                                        \
            _Pragma("unroll")                                                 \
            for (int ni = 0; ni < 4; ni++)                                    \
                wmma::mma_sync(acc[mi][ni], alf[mi], bhf[ni], acc[mi][ni]);   \
        _Pragma("unroll")                                                     \
        for (int ni = 0; ni < 4; ni++)                                        \
            wmma::load_matrix_sync(blf[ni],                                   \
                (Bs) + (warp_n * 64 + ni * 16) * (STRIDE) + (COFF) + 16,      \
                (STRIDE));                                                    \
        _Pragma("unroll")                                                     \
        for (int mi = 0; mi < 2; mi++)                                        \
            _Pragma("unroll")                                                 \
            for (int ni = 0; ni < 4; ni++)                                    \
                wmma::mma_sync(acc[mi][ni], ahf[mi], blf[ni], acc[mi][ni]);   \
    } while (0)

// 3-term split math, warp tile 32x32 (conv): acc[2][2], lower reg pressure
#define WMMA_MATH32(As, Bs)                                                   \
    do {                                                                      \
        AFrag ahf[2], alf[2];                                                 \
        BFrag bhf[2], blf[2];                                                 \
        _Pragma("unroll")                                                     \
        for (int mi = 0; mi < 2; mi++)                                        \
            wmma::load_matrix_sync(ahf[mi],                                   \
                (As) + (warp_m * 32 + mi * 16) * OP_STRIDE, OP_STRIDE);       \
        _Pragma("unroll")                                                     \
        for (int ni = 0; ni < 2; ni++)                                        \
            wmma::load_matrix_sync(bhf[ni],                                   \
                (Bs) + (warp_n * 32 + ni * 16) * OP_STRIDE, OP_STRIDE);       \
        _Pragma("unroll")                                                     \
        for (int mi = 0; mi < 2; mi++)                                        \
            _Pragma("unroll")                                                 \
            for (int ni = 0; ni < 2; ni++)                                    \
                wmma::mma_sync(acc[mi][ni], ahf[mi], bhf[ni], acc[mi][ni]);   \
        _Pragma("unroll")                                                     \
        for (int mi = 0; mi < 2; mi++)                                        \
            wmma::load_matrix_sync(alf[mi],                                   \
                (As) + (warp_m * 32 + mi * 16) * OP_STRIDE + 16, OP_STRIDE);  \
        _Pragma("unroll")                                                     \
        for (int mi = 0; mi < 2; mi++)                                        \
            _Pragma("unroll")                                                 \
            for (int ni = 0; ni < 2; ni++)                                    \
                wmma::mma_sync(acc[mi][ni], alf[mi], bhf[ni], acc[mi][ni]);   \
        _Pragma("unroll")                                                     \
        for (int ni = 0; ni < 2; ni++)                                        \
            wmma::load_matrix_sync(blf[ni],                                   \
                (Bs) + (warp_n * 32 + ni * 16) * OP_STRIDE + 16, OP_STRIDE);  \
        _Pragma("unroll")                                                     \
        for (int mi = 0; mi < 2; mi++)                                        \
            _Pragma("unroll")                                                 \
            for (int ni = 0; ni < 2; ni++)                                    \
                wmma::mma_sync(acc[mi][ni], ahf[mi], blf[ni], acc[mi][ni]);   \
    } while (0)

// ---------------------------------------------------------------------------
// Kernel 0a/0b: pack + split weights (chunk row: [wh(16)|wl(16)])
// ---------------------------------------------------------------------------
__global__ __launch_bounds__(256)
void prep_w_kernel(const float* __restrict__ w_dil) {
    int idx = blockIdx.x * 256 + threadIdx.x;
    if (idx >= DEPTH * HID * 768) return;
    int q  = idx % 768;
    int co = (idx / 768) % HID;
    int L  = idx / (768 * HID);
    int ci = q / 3, k = q - 3 * ci;
    float v = w_dil[(((size_t)L * HID + co) * HID + ci) * 3 + k];
    __nv_bfloat16 hi = __float2bfloat16(v);
    __nv_bfloat16 lo = __float2bfloat16(v - __bfloat162float(hi));
    int c = q >> 4, t = q & 15;
    __nv_bfloat16* row = &g_wpack[L][co][c * CH_K];
    row[t]      = hi;
    row[16 + t] = lo;
}

__global__ __launch_bounds__(256)
void prep_wp_kernel(const float* __restrict__ w_proj) {
    int idx = blockIdx.x * 256 + threadIdx.x;
    if (idx >= HID * MOTIF) return;
    int m = idx % MOTIF;
    int c = idx / MOTIF;
    float v = w_proj[(size_t)c * MOTIF + m];
    __nv_bfloat16 hi = __float2bfloat16(v);
    __nv_bfloat16 lo = __float2bfloat16(v - __bfloat162float(hi));
    int ch = m >> 4, t = m & 15;
    __nv_bfloat16* row = &g_wppack[c][ch * CH_K];
    row[t]      = hi;
    row[16 + t] = lo;
}

// ---------------------------------------------------------------------------
// Kernel 1: 1x1 motif projection via WMMA (unchanged, proven)
// ---------------------------------------------------------------------------
__global__ __launch_bounds__(256, 2)
void proj_wmma_kernel(const float* __restrict__ x,
                      const float* __restrict__ bias) {
    extern __shared__ __align__(16) char smraw[];
    const uint32_t smb = (uint32_t)__cvta_generic_to_shared(smraw);

    const int tid    = threadIdx.x;
    const int wid    = tid >> 5;
    const int warp_m = wid & 3;
    const int warp_n = wid >> 2;
    const int gl0    = blockIdx.x * 128;
    const int nh     = blockIdx.y;

    const int al = tid & 127;
    const int ah = tid >> 7;
    const int brow  = tid >> 1;
    const int bhalf = tid & 1;
    const __nv_bfloat16* wrow = &g_wppack[nh * 128 + brow][0];
    const float* xrow = x + (size_t)(gl0 + al) * MOTIF + ah * 8;

    CFrag acc[2][4];
#pragma unroll
    for (int mi = 0; mi < 2; mi++)
#pragma unroll
        for (int ni = 0; ni < 4; ni++) wmma::fill_fragment(acc[mi][ni], 0.f);

    float f[8];

    auto issue_b = [&](int c, int b) {
        const uint32_t dst = smb + (b ? P_B1 : P_B0) + brow * 80 + bhalf * 32;
        const __nv_bfloat16* sp = wrow + c * CH_K + bhalf * 16;
        cpa16(dst, sp);
        cpa16(dst + 16, sp + 8);
        cpa_commit();
    };
    auto a_ld = [&](int c) {
        float4 v0 = *(const float4*)(xrow + c * 16);
        float4 v1 = *(const float4*)(xrow + c * 16 + 4);
        f[0] = v0.x; f[1] = v0.y; f[2] = v0.z; f[3] = v0.w;
        f[4] = v1.x; f[5] = v1.y; f[6] = v1.z; f[7] = v1.w;
    };
    auto a_st = [&](int b) {
        float h[8], l[8];
#pragma unroll
        for (int j = 0; j < 8; j++) {
            h[j] = __bfloat162float(__float2bfloat16(f[j]));
            l[j] = f[j] - h[j];
        }
        uint4 H, L;
        H.x = pack2(h[0], h[1]); H.y = pack2(h[2], h[3]);
        H.z = pack2(h[4], h[5]); H.w = pack2(h[6], h[7]);
        L.x = pack2(l[0], l[1]); L.y = pack2(l[2], l[3]);
        L.z = pack2(l[4], l[5]); L.w = pack2(l[6], l[7]);
        const uint32_t ab = smb + (b ? P_A1 : P_A0) + al * 80 + ah * 16;
        asm volatile("st.shared.v4.b32 [%0], {%1, %2, %3, %4};"
            :: "r"(ab), "r"(H.x), "r"(H.y), "r"(H.z), "r"(H.w) : "memory");
        asm volatile("st.shared.v4.b32 [%0], {%1, %2, %3, %4};"
            :: "r"(ab + 32), "r"(L.x), "r"(L.y), "r"(L.z), "r"(L.w) : "memory");
    };

    issue_b(0, 0);
    a_ld(0);
    a_st(0);
    cpa_wait0();
    __syncthreads();

#pragma unroll 1
    for (int c = 0; c < NCHUNK_P; c++) {
        const int cb = c & 1;
        if (c + 1 < NCHUNK_P) { issue_b(c + 1, cb ^ 1); a_ld(c + 1); }

        const __nv_bfloat16* As =
            reinterpret_cast<const __nv_bfloat16*>(smraw + (cb ? P_A1 : P_A0));
        const __nv_bfloat16* Bs =
            reinterpret_cast<const __nv_bfloat16*>(smraw + (cb ? P_B1 : P_B0));
        WMMA_MATH_S(As, Bs, OP_STRIDE, 0);

        if (c + 1 < NCHUNK_P) { a_st(cb ^ 1); cpa_wait0(); }
        __syncthreads();
    }

    float* Ds = reinterpret_cast<float*>(smraw);
#pragma unroll
    for (int mi = 0; mi < 2; mi++)
#pragma unroll
        for (int ni = 0; ni < 4; ni++)
            wmma::store_matrix_sync(
                Ds + (warp_n * 64 + ni * 16) * D_LD + (warp_m * 32 + mi * 16),
                acc[mi][ni], D_LD, wmma::mem_col_major);
    __syncthreads();

#pragma unroll 1
    for (int idx = tid; idx < 128 * 128; idx += 256) {
        const int cl = idx >> 7;
        const int gi = idx & 127;
        const int gl = gl0 + gi;
        const int n  = gl / PSIZE;
        const int l  = gl - n * PSIZE;
        const int cg = nh * 128 + cl;
        const float v = Ds[cl * D_LD + gi] + bias[cg];
        const size_t off = ((size_t)n * HID + cg) * MAXLEN + l;
        g_buf[0][off]   = v;
        g_split[0][off] = pack_split(v);
    }
}

// ---------------------------------------------------------------------------
// Kernel 2: dilated conv via WMMA; CTA tile 128l x 64co, warp tile 32x32,
// 3 CTAs/SM (24 warps) for latency hiding. 16-q chunks, double-buffered.
// ---------------------------------------------------------------------------
template <int DIL, int LEN_OUT>
__global__ __launch_bounds__(256, 3)
void conv_wmma_kernel(int src, int layer, const float* __restrict__ bias) {
    extern __shared__ __align__(16) char smraw[];
    const uint32_t smb = (uint32_t)__cvta_generic_to_shared(smraw);

    const int tid    = threadIdx.x;
    const int wid    = tid >> 5;
    const int warp_m = wid & 3;          // 0..3 -> m0 = 32*warp_m
    const int warp_n = wid >> 2;         // 0..1 -> n0 = 32*warp_n
    const int l0     = blockIdx.x * 128;
    const int nh     = blockIdx.y;       // co quarter (0..3)
    const int n      = blockIdx.z;       // peak

    const unsigned* __restrict__ xsrc = g_split[src] + (size_t)n * HID * MAXLEN;
    const float* __restrict__ resbase = g_buf[src] + (size_t)n * HID * MAXLEN;
    float* __restrict__ outbase   = g_buf[src ^ 1] + (size_t)n * HID * MAXLEN;
    unsigned* __restrict__ outsplit =
        g_split[src ^ 1] + (size_t)n * HID * MAXLEN;

    const int al = tid & 127;            // A row (l)
    const int ah = tid >> 7;             // q half (0/1)
    const int brow = tid >> 2;           // B row (co in quarter), 0..63
    const int bq   = tid & 3;            // 16B granule
    const __nv_bfloat16* wrow = &g_wpack[layer][nh * 64 + brow][0];

    CFrag acc[2][2];
#pragma unroll
    for (int mi = 0; mi < 2; mi++)
#pragma unroll
        for (int ni = 0; ni < 2; ni++) wmma::fill_fragment(acc[mi][ni], 0.f);

    unsigned areg[8];

    auto issue_b = [&](int c, int b) {
        const uint32_t dst = smb + (b ? CV_B1 : CV_B0) + brow * 80 + bq * 16;
        cpa16(dst, wrow + c * CH_K + bq * 8);
        cpa_commit();
    };
    auto a_ld = [&](int c) {
#pragma unroll
        for (int j = 0; j < 8; j++) {
            const int q  = c * 16 + ah * 8 + j;
            const int ci = q / 3;
            const int k  = q - 3 * ci;
            areg[j] = xsrc[(size_t)ci * MAXLEN + l0 + al + k * DIL];
        }
    };
    auto a_st = [&](int b) {
        uint4 H, L;
        asm("prmt.b32 %0, %1, %2, 0x5410;" : "=r"(H.x) : "r"(areg[0]), "r"(areg[1]));
        asm("prmt.b32 %0, %1, %2, 0x5410;" : "=r"(H.y) : "r"(areg[2]), "r"(areg[3]));
        asm("prmt.b32 %0, %1, %2, 0x5410;" : "=r"(H.z) : "r"(areg[4]), "r"(areg[5]));
        asm("prmt.b32 %0, %1, %2, 0x5410;" : "=r"(H.w) : "r"(areg[6]), "r"(areg[7]));
        asm("prmt.b32 %0, %1, %2, 0x7632;" : "=r"(L.x) : "r"(areg[0]), "r"(areg[1]));
        asm("prmt.b32 %0, %1, %2, 0x7632;" : "=r"(L.y) : "r"(areg[2]), "r"(areg[3]));
        asm("prmt.b32 %0, %1, %2, 0x7632;" : "=r"(L.z) : "r"(areg[4]), "r"(areg[5]));
        asm("prmt.b32 %0, %1, %2, 0x7632;" : "=r"(L.w) : "r"(areg[6]), "r"(areg[7]));
        const uint32_t ab = smb + (b ? CV_A1 : CV_A0) + al * 80 + ah * 16;
        asm volatile("st.shared.v4.b32 [%0], {%1, %2, %3, %4};"
            :: "r"(ab), "r"(H.x), "r"(H.y), "r"(H.z), "r"(H.w) : "memory");
        asm volatile("st.shared.v4.b32 [%0], {%1, %2, %3, %4};"
            :: "r"(ab + 32), "r"(L.x), "r"(L.y), "r"(L.z), "r"(L.w) : "memory");
    };

    issue_b(0, 0);
    a_ld(0);
    a_st(0);
    cpa_wait0();
    __syncthreads();

#pragma unroll 1
    for (int c = 0; c < NCHUNK16; c++) {
        const int cb = c & 1;
        if (c + 1 < NCHUNK16) { issue_b(c + 1, cb ^ 1); a_ld(c + 1); }

        const __nv_bfloat16* As =
            reinterpret_cast<const __nv_bfloat16*>(smraw + (cb ? CV_A1 : CV_A0));
        const __nv_bfloat16* Bs =
            reinterpret_cast<const __nv_bfloat16*>(smraw + (cb ? CV_B1 : CV_B0));
        WMMA_MATH32(As, Bs);

        if (c + 1 < NCHUNK16) { a_st(cb ^ 1); cpa_wait0(); }
        __syncthreads();
    }

    // epilogue: acc -> smem D [co][l], then fused bias+relu+residual out
    float* Ds = reinterpret_cast<float*>(smraw);
#pragma unroll
    for (int mi = 0; mi < 2; mi++)
#pragma unroll
        for (int ni = 0; ni < 2; ni++)
            wmma::store_matrix_sync(
                Ds + (warp_n * 32 + ni * 16) * D_LD + (warp_m * 32 + mi * 16),
                acc[mi][ni], D_LD, wmma::mem_col_major);
    __syncthreads();

#pragma unroll 1
    for (int idx = tid; idx < 64 * 128; idx += 256) {
        const int co = idx >> 7;           // 0..63 in this quarter
        const int l  = idx & 127;
        if (l0 + l < LEN_OUT) {
            const int co_g = nh * 64 + co;
            const float d  = Ds[co * D_LD + l];
            const float v  = fmaxf(d + bias[co_g], 0.f)
                           + resbase[(size_t)co_g * MAXLEN + l0 + l + DIL];
            outbase[(size_t)co_g * MAXLEN + l0 + l]  = v;
            outsplit[(size_t)co_g * MAXLEN + l0 + l] = pack_split(v);
        }
    }
}

// ---------------------------------------------------------------------------
// Kernel 3: per-(peak, channel) mean over length
// ---------------------------------------------------------------------------
__global__ __launch_bounds__(256)
void mean_kernel(int src, int len) {
    const float* __restrict__ in = g_buf[src];
    const int row  = blockIdx.x * 8 + (threadIdx.x >> 5);
    const int lane = threadIdx.x & 31;
    const float* p = in + (size_t)row * MAXLEN;
    float s = 0.f;
    for (int l = lane; l < len; l += 32) s += p[l];
#pragma unroll
    for (int o = 16; o; o >>= 1) s += __shfl_xor_sync(0xFFFFFFFFu, s, o);
    if (lane == 0) g_mean[row] = s / (float)len;
}

// ---------------------------------------------------------------------------
// Kernel 4: atpm head
// ---------------------------------------------------------------------------
__global__ __launch_bounds__(256)
void atpm_kernel(const float* __restrict__ w, const float* __restrict__ b,
                 float* __restrict__ out) {
    __shared__ float sh[256];
    const int n = blockIdx.x;
    const int t = threadIdx.x;
    sh[t] = g_mean[n * HID + t] * w[t];
    __syncthreads();
    for (int s = 128; s > 0; s >>= 1) {
        if (t < s) sh[t] += sh[t + s];
        __syncthreads();
    }
    if (t == 0) out[n] = softplus_f(sh[0] + b[0]);
}

// ---------------------------------------------------------------------------
// Kernel 5: profile conv (K=75, 256 -> 1) + softplus
// ---------------------------------------------------------------------------
__global__ __launch_bounds__(256)
void prof_kernel(int src, const float* __restrict__ wp,
                 const float* __restrict__ bp, float* __restrict__ out,
                 int len_in, int len_out) {
    __shared__ float hrow[512];
    __shared__ float wrow[80];
    const float* __restrict__ in = g_buf[src];
    const int n = blockIdx.x;
    const int t = threadIdx.x;
    const int l0 = t;
    const int l1 = t + 256;

    float acc0 = 0.f, acc1 = 0.f;
    for (int c = 0; c < HID; c++) {
        for (int l = t; l < len_in; l += 256)
            hrow[l] = in[((size_t)n * HID + c) * MAXLEN + l];
        if (t < PROF_K) wrow[t] = wp[c * PROF_K + t];
        __syncthreads();

#pragma unroll 5
        for (int k = 0; k < PROF_K; k++)
            acc0 = fmaf(hrow[l0 + k], wrow[k], acc0);
        if (l1 < len_out) {
#pragma unroll 5
            for (int k = 0; k < PROF_K; k++)
                acc1 = fmaf(hrow[l1 + k], wrow[k], acc1);
        }
        __syncthreads();
    }
    const float bv = bp[0];
    out[PEAKS + (size_t)n * len_out + l0] = softplus_f(acc0 + bv);
    if (l1 < len_out)
        out[PEAKS + (size_t)n * len_out + l1] = softplus_f(acc1 + bv);
}

// ---------------------------------------------------------------------------
// Launch
// ---------------------------------------------------------------------------
template <int DIL, int LEN_OUT>
static void launch_conv(int src, int layer, const float* b) {
    static bool attr_done = false;
    if (!attr_done) {
        cudaFuncSetAttribute(conv_wmma_kernel<DIL, LEN_OUT>,
                             cudaFuncAttributeMaxDynamicSharedMemorySize,
                             CONV_SMEM);
        attr_done = true;
    }
    conv_wmma_kernel<DIL, LEN_OUT>
        <<<dim3((LEN_OUT + 127) / 128, 4, PEAKS), 256, CONV_SMEM>>>(
            src, layer, b);
}

extern "C" void kernel_launch(void* const* d_in, const int* in_sizes, int n_in,
                              void* d_out, int out_size) {
    const float* x = (const float*)d_in[0];

    int iw = -1;
    for (int i = 1; i < n_in; i++)
        if (in_sizes[i] == MOTIF * HID) { iw = i; break; }

    const float* w_proj = (const float*)d_in[iw + 0];
    const float* b_proj = (const float*)d_in[iw + 1];
    const float* w_dil  = (const float*)d_in[iw + 2];
    const float* b_dil  = (const float*)d_in[iw + 3];
    const float* w_prof = (const float*)d_in[iw + 4];
    const float* b_prof = (const float*)d_in[iw + 5];
    const float* w_atpm = (const float*)d_in[iw + 6];
    const float* b_atpm = (const float*)d_in[iw + 7];
    float* out = (float*)d_out;

    static bool proj_attr = false;
    if (!proj_attr) {
        cudaFuncSetAttribute(proj_wmma_kernel,
                             cudaFuncAttributeMaxDynamicSharedMemorySize,
                             PROJ_SMEM);
        proj_attr = true;
    }

    // 0) pack + split weights
    prep_w_kernel<<<(DEPTH * HID * 768 + 255) / 256, 256>>>(w_dil);
    prep_wp_kernel<<<(HID * MOTIF + 255) / 256, 256>>>(w_proj);

    // 1) projection (WMMA) -> g_buf[0] + g_split[0]
    proj_wmma_kernel<<<dim3(GL_TOTAL / 128, 2, 1), 256, PROJ_SMEM>>>(x, b_proj);

    // 2) dilated conv tower (WMMA), lengths 1000->996->...->492
    launch_conv<  2, 996>(0, 0, b_dil + 0 * HID);
    launch_conv<  4, 988>(1, 1, b_dil + 1 * HID);
    launch_conv<  8, 972>(0, 2, b_dil + 2 * HID);
    launch_conv< 16, 940>(1, 3, b_dil + 3 * HID);
    launch_conv< 32, 876>(0, 4, b_dil + 4 * HID);
    launch_conv< 64, 748>(1, 5, b_dil + 5 * HID);
    launch_conv<128, 492>(0, 6, b_dil + 6 * HID);
    const int src = 1;   // final fp32 map in g_buf[1], len = 492
    const int len = 492;

    // 3) mean over length
    mean_kernel<<<(PEAKS * HID) / 8, 256>>>(src, len);

    // 4) atpm head -> out[0..127]
    atpm_kernel<<<PEAKS, 256>>>(w_atpm, b_atpm, out);

    // 5) profile conv -> out[128 .. 128 + 128*418)
    prof_kernel<<<PEAKS, 256>>>(src, w_prof, b_prof, out, len, len - PROF_K + 1);
}